// round 1
// baseline (speedup 1.0000x reference)
#include <cuda_runtime.h>
#include <cstdint>

// Problem constants
#define NG    4          // n_graph
#define NH    12         // heads
#define BHD   48         // NG*NH
#define NNODE 1024
#define EDIM  768
#define HD    64
#define QSCALE 0.125f    // hd^-0.5
#define MROWS 4096       // NNODE*NG

// Scratch (no cudaMalloc allowed)
__device__ float g_q[BHD * NNODE * HD];
__device__ float g_k[BHD * NNODE * HD];
__device__ float g_v[BHD * NNODE * HD];
__device__ float g_attn[MROWS * EDIM];
__device__ int   g_mask_kind;   // 0 = uint8, 1 = int32, 2 = float32

// ---------------------------------------------------------------------------
// Detect how the bool mask was serialized. Looks at the first 4096 bytes
// (valid for all candidate dtypes since the mask has 4096 elements).
//   int32 0/1  : bytes 1..3 of each word are always 0, byte0 sometimes 1
//   float 0/1.0: byte0 always 0 (0x3F800000 / 0x00000000)
//   uint8 0/1  : bytes at all positions randomly nonzero
// ---------------------------------------------------------------------------
__global__ void detect_mask_kernel(const uint8_t* __restrict__ m) {
    __shared__ int or_b0, or_b123;
    if (threadIdx.x == 0) { or_b0 = 0; or_b123 = 0; }
    __syncthreads();
    int a0 = 0, a123 = 0;
    for (int w = threadIdx.x; w < 1024; w += blockDim.x) {
        a0   |= m[4 * w];
        a123 |= m[4 * w + 1] | m[4 * w + 2] | m[4 * w + 3];
    }
    if (a0)   atomicOr(&or_b0, 1);
    if (a123) atomicOr(&or_b123, 1);
    __syncthreads();
    if (threadIdx.x == 0) {
        if (or_b0 == 0)            g_mask_kind = 2;  // float32
        else if (or_b123 == 0)     g_mask_kind = 1;  // int32
        else                       g_mask_kind = 0;  // uint8/bool
    }
}

// ---------------------------------------------------------------------------
// Kernel 1: qkv = query @ W_in^T + b_in, scattered into g_q/g_k/g_v
// A: [4096, 768] (row = n*4 + b), W: [2304, 768], bias: [2304]
// 64x64 block tile, 16x16 threads, 4x4 micro tile, K-tile = 16
// ---------------------------------------------------------------------------
__global__ __launch_bounds__(256) void qkv_gemm_kernel(
    const float* __restrict__ A,
    const float* __restrict__ W,
    const float* __restrict__ bias)
{
    __shared__ float As[16][64];
    __shared__ float Bs[16][64];
    const int tx = threadIdx.x, ty = threadIdx.y;
    const int tid = ty * 16 + tx;
    const int m0 = blockIdx.x * 64;
    const int n0 = blockIdx.y * 64;
    const int lr = tid >> 2;
    const int lc = (tid & 3) * 4;

    float acc[4][4] = {};
    for (int k0 = 0; k0 < EDIM; k0 += 16) {
        float4 a4 = *(const float4*)(A + (size_t)(m0 + lr) * EDIM + k0 + lc);
        float4 b4 = *(const float4*)(W + (size_t)(n0 + lr) * EDIM + k0 + lc);
        As[lc + 0][lr] = a4.x; As[lc + 1][lr] = a4.y;
        As[lc + 2][lr] = a4.z; As[lc + 3][lr] = a4.w;
        Bs[lc + 0][lr] = b4.x; Bs[lc + 1][lr] = b4.y;
        Bs[lc + 2][lr] = b4.z; Bs[lc + 3][lr] = b4.w;
        __syncthreads();
#pragma unroll
        for (int k = 0; k < 16; k++) {
            float4 av = *(const float4*)&As[k][ty * 4];
            float4 bv = *(const float4*)&Bs[k][tx * 4];
            float am[4] = {av.x, av.y, av.z, av.w};
            float bn[4] = {bv.x, bv.y, bv.z, bv.w};
#pragma unroll
            for (int i = 0; i < 4; i++)
#pragma unroll
                for (int j = 0; j < 4; j++)
                    acc[i][j] += am[i] * bn[j];
        }
        __syncthreads();
    }

#pragma unroll
    for (int i = 0; i < 4; i++) {
        int row = m0 + ty * 4 + i;
        int n = row >> 2, bg = row & 3;
#pragma unroll
        for (int j = 0; j < 4; j++) {
            int col = n0 + tx * 4 + j;
            float v = acc[i][j] + bias[col];
            int sec = col / EDIM;
            int e = col - sec * EDIM;
            int h = e >> 6, d = e & 63;
            int bh = bg * NH + h;
            size_t idx = ((size_t)bh * NNODE + n) * HD + d;
            if (sec == 0)      g_q[idx] = v * QSCALE;
            else if (sec == 1) g_k[idx] = v;
            else               g_v[idx] = v;
        }
    }
}

// ---------------------------------------------------------------------------
// Kernel 2: flash attention (fp32). One CTA per (64 query rows, head).
// Online softmax over 16 key tiles of 64. Bias fused.
// ---------------------------------------------------------------------------
#define SPITCH 65
__global__ __launch_bounds__(256) void attn_kernel(const float* __restrict__ bias)
{
    extern __shared__ float sm[];
    float* Qs = sm;                   // [64][65]
    float* Ks = sm + 64 * SPITCH;     // [64][65]
    float* Vs = sm + 2 * 64 * SPITCH; // [64][65]
    float* Ps = sm + 3 * 64 * SPITCH; // [64][65]

    const int tx = threadIdx.x, ty = threadIdx.y;
    const int tid = ty * 16 + tx;
    const int bh = blockIdx.y;
    const int n0 = blockIdx.x * 64;
    const int r0 = ty * 4, c0 = tx * 4;

    // Load Q tile
    const float* qptr = g_q + ((size_t)bh * NNODE + n0) * HD;
    for (int t = tid; t < 1024; t += 256) {
        int r = t >> 4, c = (t & 15) * 4;
        float4 v4 = *(const float4*)(qptr + r * HD + c);
        float* dst = Qs + r * SPITCH + c;
        dst[0] = v4.x; dst[1] = v4.y; dst[2] = v4.z; dst[3] = v4.w;
    }

    float o[4][4] = {};
    float mrow[4], lrow[4];
#pragma unroll
    for (int i = 0; i < 4; i++) { mrow[i] = -1e30f; lrow[i] = 0.0f; }

    const float* bbase = bias + ((size_t)bh << 20) + (size_t)n0 * NNODE;

    for (int t = 0; t < 16; t++) {
        const int m0 = t * 64;
        __syncthreads();  // previous PV done before overwriting K/V
        const float* kptr = g_k + ((size_t)bh * NNODE + m0) * HD;
        const float* vptr = g_v + ((size_t)bh * NNODE + m0) * HD;
        for (int q = tid; q < 1024; q += 256) {
            int r = q >> 4, c = (q & 15) * 4;
            float4 kk = *(const float4*)(kptr + r * HD + c);
            float* kd = Ks + r * SPITCH + c;
            kd[0] = kk.x; kd[1] = kk.y; kd[2] = kk.z; kd[3] = kk.w;
            float4 vv = *(const float4*)(vptr + r * HD + c);
            float* vd = Vs + r * SPITCH + c;
            vd[0] = vv.x; vd[1] = vv.y; vd[2] = vv.z; vd[3] = vv.w;
        }
        __syncthreads();

        // S = Q K^T  (4x4 micro tile per thread)
        float s[4][4] = {};
#pragma unroll 16
        for (int d = 0; d < 64; d++) {
            float qv[4], kv[4];
#pragma unroll
            for (int i = 0; i < 4; i++) qv[i] = Qs[(r0 + i) * SPITCH + d];
#pragma unroll
            for (int j = 0; j < 4; j++) kv[j] = Ks[(c0 + j) * SPITCH + d];
#pragma unroll
            for (int i = 0; i < 4; i++)
#pragma unroll
                for (int j = 0; j < 4; j++)
                    s[i][j] += qv[i] * kv[j];
        }

        // + bias, online softmax
#pragma unroll
        for (int i = 0; i < 4; i++) {
            float4 bb = *(const float4*)(bbase + (size_t)(r0 + i) * NNODE + m0 + c0);
            s[i][0] += bb.x; s[i][1] += bb.y; s[i][2] += bb.z; s[i][3] += bb.w;

            float mt = fmaxf(fmaxf(s[i][0], s[i][1]), fmaxf(s[i][2], s[i][3]));
#pragma unroll
            for (int off = 8; off >= 1; off >>= 1)
                mt = fmaxf(mt, __shfl_xor_sync(0xffffffffu, mt, off, 16));
            float mnew = fmaxf(mrow[i], mt);
            float alpha = __expf(mrow[i] - mnew);
            mrow[i] = mnew;
            float rs = 0.0f;
#pragma unroll
            for (int j = 0; j < 4; j++) { s[i][j] = __expf(s[i][j] - mnew); rs += s[i][j]; }
#pragma unroll
            for (int off = 8; off >= 1; off >>= 1)
                rs += __shfl_xor_sync(0xffffffffu, rs, off, 16);
            lrow[i] = lrow[i] * alpha + rs;
#pragma unroll
            for (int j = 0; j < 4; j++) o[i][j] *= alpha;
        }

        // write P
#pragma unroll
        for (int i = 0; i < 4; i++)
#pragma unroll
            for (int j = 0; j < 4; j++)
                Ps[(r0 + i) * SPITCH + c0 + j] = s[i][j];
        __syncthreads();

        // O += P V
#pragma unroll 16
        for (int mm = 0; mm < 64; mm++) {
            float pv[4], vv[4];
#pragma unroll
            for (int i = 0; i < 4; i++) pv[i] = Ps[(r0 + i) * SPITCH + mm];
#pragma unroll
            for (int j = 0; j < 4; j++) vv[j] = Vs[mm * SPITCH + c0 + j];
#pragma unroll
            for (int i = 0; i < 4; i++)
#pragma unroll
                for (int j = 0; j < 4; j++)
                    o[i][j] += pv[i] * vv[j];
        }
    }

    // normalize + store to [N, B, E] layout
    const int bg = bh / NH, h = bh - bg * NH;
#pragma unroll
    for (int i = 0; i < 4; i++) {
        int n = n0 + r0 + i;
        float inv = 1.0f / lrow[i];
        float4 ov;
        ov.x = o[i][0] * inv; ov.y = o[i][1] * inv;
        ov.z = o[i][2] * inv; ov.w = o[i][3] * inv;
        *(float4*)(g_attn + ((size_t)n * NG + bg) * EDIM + h * HD + c0) = ov;
    }
}

// ---------------------------------------------------------------------------
// Kernel 3: out = attn @ W_out^T + b_out, masked
// ---------------------------------------------------------------------------
__global__ __launch_bounds__(256) void out_gemm_kernel(
    const float* __restrict__ W,
    const float* __restrict__ bias,
    const void*  __restrict__ maskp,
    float* __restrict__ out)
{
    __shared__ float As[16][64];
    __shared__ float Bs[16][64];
    const int tx = threadIdx.x, ty = threadIdx.y;
    const int tid = ty * 16 + tx;
    const int m0 = blockIdx.x * 64;
    const int n0 = blockIdx.y * 64;
    const int lr = tid >> 2;
    const int lc = (tid & 3) * 4;

    float acc[4][4] = {};
    for (int k0 = 0; k0 < EDIM; k0 += 16) {
        float4 a4 = *(const float4*)(g_attn + (size_t)(m0 + lr) * EDIM + k0 + lc);
        float4 b4 = *(const float4*)(W + (size_t)(n0 + lr) * EDIM + k0 + lc);
        As[lc + 0][lr] = a4.x; As[lc + 1][lr] = a4.y;
        As[lc + 2][lr] = a4.z; As[lc + 3][lr] = a4.w;
        Bs[lc + 0][lr] = b4.x; Bs[lc + 1][lr] = b4.y;
        Bs[lc + 2][lr] = b4.z; Bs[lc + 3][lr] = b4.w;
        __syncthreads();
#pragma unroll
        for (int k = 0; k < 16; k++) {
            float4 av = *(const float4*)&As[k][ty * 4];
            float4 bv = *(const float4*)&Bs[k][tx * 4];
            float am[4] = {av.x, av.y, av.z, av.w};
            float bn[4] = {bv.x, bv.y, bv.z, bv.w};
#pragma unroll
            for (int i = 0; i < 4; i++)
#pragma unroll
                for (int j = 0; j < 4; j++)
                    acc[i][j] += am[i] * bn[j];
        }
        __syncthreads();
    }

    const int mkind = g_mask_kind;
#pragma unroll
    for (int i = 0; i < 4; i++) {
        int row = m0 + ty * 4 + i;
        int n = row >> 2, bg = row & 3;
        bool keep;
        int midx = bg * NNODE + n;
        if (mkind == 1)      keep = ((const int*)maskp)[midx] != 0;
        else if (mkind == 2) keep = ((const float*)maskp)[midx] != 0.0f;
        else                 keep = ((const uint8_t*)maskp)[midx] != 0;
#pragma unroll
        for (int j = 0; j < 4; j++) {
            int col = n0 + tx * 4 + j;
            float v = acc[i][j] + bias[col];
            out[(size_t)row * EDIM + col] = keep ? v : 0.0f;
        }
    }
}

// ---------------------------------------------------------------------------
extern "C" void kernel_launch(void* const* d_in, const int* in_sizes, int n_in,
                              void* d_out, int out_size) {
    const float* query     = (const float*)d_in[0];
    const float* attn_bias = (const float*)d_in[1];
    const void*  mask      = d_in[2];
    const float* W_in      = (const float*)d_in[3];
    const float* b_in      = (const float*)d_in[4];
    const float* W_out     = (const float*)d_in[5];
    const float* b_out     = (const float*)d_in[6];
    float* out = (float*)d_out;

    detect_mask_kernel<<<1, 256>>>((const uint8_t*)mask);

    dim3 blk(16, 16);
    qkv_gemm_kernel<<<dim3(64, 36), blk>>>(query, W_in, b_in);

    const int attn_smem = 4 * 64 * SPITCH * (int)sizeof(float);  // 66560 B
    cudaFuncSetAttribute((const void*)attn_kernel,
                         cudaFuncAttributeMaxDynamicSharedMemorySize, attn_smem);
    attn_kernel<<<dim3(16, BHD), blk, attn_smem>>>(attn_bias);

    out_gemm_kernel<<<dim3(64, 12), blk>>>(W_out, b_out, mask, out);
}

// round 2
// speedup vs baseline: 2.0765x; 2.0765x over previous
#include <cuda_runtime.h>
#include <cuda_bf16.h>
#include <cstdint>

#define NG    4
#define NH    12
#define BHD   48
#define NNODE 1024
#define EDIM  768
#define HD    64
#define QSCALE 0.125f
#define MROWS 4096

// Scratch (no cudaMalloc allowed)
__device__ __nv_bfloat16 g_qh[BHD * NNODE * HD];
__device__ __nv_bfloat16 g_ql[BHD * NNODE * HD];
__device__ __nv_bfloat16 g_kh[BHD * NNODE * HD];
__device__ __nv_bfloat16 g_kl[BHD * NNODE * HD];
__device__ __nv_bfloat16 g_vh[BHD * NNODE * HD];
__device__ __nv_bfloat16 g_vl[BHD * NNODE * HD];
__device__ float g_attn[MROWS * EDIM];
__device__ int   g_mask_kind;

// ---------------------------------------------------------------------------
// helpers
// ---------------------------------------------------------------------------
__device__ __forceinline__ uint32_t smem_u32(const void* p) {
    return (uint32_t)__cvta_generic_to_shared(p);
}
__device__ __forceinline__ void ldmx4(uint32_t& r0, uint32_t& r1, uint32_t& r2, uint32_t& r3, uint32_t a) {
    asm volatile("ldmatrix.sync.aligned.m8n8.x4.shared.b16 {%0,%1,%2,%3},[%4];\n"
                 : "=r"(r0), "=r"(r1), "=r"(r2), "=r"(r3) : "r"(a));
}
__device__ __forceinline__ void ldmx4t(uint32_t& r0, uint32_t& r1, uint32_t& r2, uint32_t& r3, uint32_t a) {
    asm volatile("ldmatrix.sync.aligned.m8n8.x4.trans.shared.b16 {%0,%1,%2,%3},[%4];\n"
                 : "=r"(r0), "=r"(r1), "=r"(r2), "=r"(r3) : "r"(a));
}
__device__ __forceinline__ void mma16816(float* c, const uint32_t* a, uint32_t b0, uint32_t b1) {
    asm volatile("mma.sync.aligned.m16n8k16.row.col.f32.bf16.bf16.f32 "
                 "{%0,%1,%2,%3},{%4,%5,%6,%7},{%8,%9},{%0,%1,%2,%3};\n"
                 : "+f"(c[0]), "+f"(c[1]), "+f"(c[2]), "+f"(c[3])
                 : "r"(a[0]), "r"(a[1]), "r"(a[2]), "r"(a[3]), "r"(b0), "r"(b1));
}
__device__ __forceinline__ uint32_t pack_bf16(float x, float y) {
    __nv_bfloat16 bx = __float2bfloat16_rn(x), by = __float2bfloat16_rn(y);
    uint16_t ux = *reinterpret_cast<uint16_t*>(&bx);
    uint16_t uy = *reinterpret_cast<uint16_t*>(&by);
    return (uint32_t)ux | ((uint32_t)uy << 16);
}
// split 8 consecutive floats into bf16 hi/lo 16B chunks
__device__ __forceinline__ void split8(const float* f, uint4& h, uint4& l) {
    float hv[8], lv[8];
#pragma unroll
    for (int i = 0; i < 8; i++) {
        __nv_bfloat16 b = __float2bfloat16_rn(f[i]);
        hv[i] = __bfloat162float(b);
        lv[i] = f[i] - hv[i];
    }
    h = make_uint4(pack_bf16(hv[0], hv[1]), pack_bf16(hv[2], hv[3]),
                   pack_bf16(hv[4], hv[5]), pack_bf16(hv[6], hv[7]));
    l = make_uint4(pack_bf16(lv[0], lv[1]), pack_bf16(lv[2], lv[3]),
                   pack_bf16(lv[4], lv[5]), pack_bf16(lv[6], lv[7]));
}

// ---------------------------------------------------------------------------
// mask dtype probe (bool serialization ambiguity)
// ---------------------------------------------------------------------------
__global__ void detect_mask_kernel(const uint8_t* __restrict__ m) {
    __shared__ int or_b0, or_b123;
    if (threadIdx.x == 0) { or_b0 = 0; or_b123 = 0; }
    __syncthreads();
    int a0 = 0, a123 = 0;
    for (int w = threadIdx.x; w < 1024; w += blockDim.x) {
        a0   |= m[4 * w];
        a123 |= m[4 * w + 1] | m[4 * w + 2] | m[4 * w + 3];
    }
    if (a0)   atomicOr(&or_b0, 1);
    if (a123) atomicOr(&or_b123, 1);
    __syncthreads();
    if (threadIdx.x == 0) {
        if (or_b0 == 0)        g_mask_kind = 2;   // float32
        else if (or_b123 == 0) g_mask_kind = 1;   // int32
        else                   g_mask_kind = 0;   // uint8
    }
}

// ---------------------------------------------------------------------------
// Kernel 1: qkv = query @ W_in^T + b_in  (split-bf16 3-pass MMA)
// A [4096,768] fp32, W [2304,768] fp32. Block 64x64, 4 warps, warp 32x32.
// Epilogue scatters q (scaled) / k / v as bf16 hi/lo into [BH][N][64].
// ---------------------------------------------------------------------------
__global__ __launch_bounds__(128) void qkv_gemm_kernel(
    const float* __restrict__ A, const float* __restrict__ W,
    const float* __restrict__ bias)
{
    __shared__ __align__(16) __nv_bfloat16 sAh[64 * 32], sAl[64 * 32];
    __shared__ __align__(16) __nv_bfloat16 sBh[64 * 32], sBl[64 * 32];
    const int tid = threadIdx.x, lane = tid & 31, warp = tid >> 5;
    const int wm = (warp >> 1) * 32, wn = (warp & 1) * 32;
    const int m0 = blockIdx.x * 64, n0 = blockIdx.y * 64;

    const uint32_t baAh = smem_u32(sAh), baAl = smem_u32(sAl);
    const uint32_t baBh = smem_u32(sBh), baBl = smem_u32(sBl);

    float acc[2][4][4] = {};

    for (int k0 = 0; k0 < EDIM; k0 += 32) {
#pragma unroll
        for (int p = 0; p < 2; p++) {
            int s = tid + p * 128;
            int row = s >> 2, sg = s & 3;
            int w = sg ^ (row & 3);
            float f[8];
            const float* ga = A + (size_t)(m0 + row) * EDIM + k0 + sg * 8;
            *(float4*)f       = *(const float4*)ga;
            *(float4*)(f + 4) = *(const float4*)(ga + 4);
            uint4 h, l; split8(f, h, l);
            *(uint4*)&sAh[row * 32 + w * 8] = h;
            *(uint4*)&sAl[row * 32 + w * 8] = l;
            const float* gb = W + (size_t)(n0 + row) * EDIM + k0 + sg * 8;
            *(float4*)f       = *(const float4*)gb;
            *(float4*)(f + 4) = *(const float4*)(gb + 4);
            split8(f, h, l);
            *(uint4*)&sBh[row * 32 + w * 8] = h;
            *(uint4*)&sBl[row * 32 + w * 8] = l;
        }
        __syncthreads();
#pragma unroll
        for (int kc = 0; kc < 2; kc++) {
            uint32_t ah[2][4], al[2][4], bh[2][4], bl[2][4];
#pragma unroll
            for (int mt = 0; mt < 2; mt++) {
                int row = wm + mt * 16 + (lane & 15);
                int ch = (kc * 2 + (lane >> 4)) ^ (row & 3);
                ldmx4(ah[mt][0], ah[mt][1], ah[mt][2], ah[mt][3], baAh + row * 64 + ch * 16);
                ldmx4(al[mt][0], al[mt][1], al[mt][2], al[mt][3], baAl + row * 64 + ch * 16);
            }
#pragma unroll
            for (int pr = 0; pr < 2; pr++) {
                int row = wn + pr * 16 + ((lane >> 4) << 3) + (lane & 7);
                int ch = (kc * 2 + ((lane >> 3) & 1)) ^ (row & 3);
                ldmx4(bh[pr][0], bh[pr][1], bh[pr][2], bh[pr][3], baBh + row * 64 + ch * 16);
                ldmx4(bl[pr][0], bl[pr][1], bl[pr][2], bl[pr][3], baBl + row * 64 + ch * 16);
            }
#pragma unroll
            for (int mt = 0; mt < 2; mt++)
#pragma unroll
                for (int nt = 0; nt < 4; nt++) {
                    uint32_t b0h = bh[nt >> 1][(nt & 1) * 2], b1h = bh[nt >> 1][(nt & 1) * 2 + 1];
                    uint32_t b0l = bl[nt >> 1][(nt & 1) * 2], b1l = bl[nt >> 1][(nt & 1) * 2 + 1];
                    mma16816(acc[mt][nt], ah[mt], b0h, b1h);
                    mma16816(acc[mt][nt], ah[mt], b0l, b1l);
                    mma16816(acc[mt][nt], al[mt], b0h, b1h);
                }
        }
        __syncthreads();
    }

    // epilogue: this block's 64 cols = head (by%12) of section (by/12)
    const int g = lane >> 2, c = lane & 3;
    const int sec = blockIdx.y / 12, hh = blockIdx.y % 12;
    __nv_bfloat16 *dh, *dl;
    if (sec == 0)      { dh = g_qh; dl = g_ql; }
    else if (sec == 1) { dh = g_kh; dl = g_kl; }
    else               { dh = g_vh; dl = g_vl; }

#pragma unroll
    for (int mt = 0; mt < 2; mt++)
#pragma unroll
        for (int nt = 0; nt < 4; nt++) {
            int dloc = wn + nt * 8 + 2 * c;   // 0..63 within head
            float bv0 = bias[n0 + dloc], bv1 = bias[n0 + dloc + 1];
#pragma unroll
            for (int rr = 0; rr < 2; rr++) {
                int row = m0 + wm + mt * 16 + g + rr * 8;
                int node = row >> 2, bg = row & 3;
                float v0 = acc[mt][nt][rr * 2 + 0] + bv0;
                float v1 = acc[mt][nt][rr * 2 + 1] + bv1;
                if (sec == 0) { v0 *= QSCALE; v1 *= QSCALE; }
                __nv_bfloat16 h0 = __float2bfloat16_rn(v0), h1 = __float2bfloat16_rn(v1);
                float l0 = v0 - __bfloat162float(h0);
                float l1 = v1 - __bfloat162float(h1);
                uint16_t u0 = *reinterpret_cast<uint16_t*>(&h0);
                uint16_t u1 = *reinterpret_cast<uint16_t*>(&h1);
                uint32_t ph = (uint32_t)u0 | ((uint32_t)u1 << 16);
                uint32_t pl = pack_bf16(l0, l1);
                size_t idx = (((size_t)(bg * NH + hh) * NNODE + node) * HD + dloc);
                *(uint32_t*)&dh[idx] = ph;
                *(uint32_t*)&dl[idx] = pl;
            }
        }
}

// ---------------------------------------------------------------------------
// Kernel 2: flash attention with split-bf16 MMA.
// CTA = 64 q rows x 1 head, 4 warps (16 rows each). Key tiles of 64.
// S and O live entirely in registers; softmax stats via quad shfl.
// ---------------------------------------------------------------------------
__global__ __launch_bounds__(128) void attn_kernel(const float* __restrict__ bias)
{
    __shared__ __align__(16) __nv_bfloat16 sQh[64 * 64], sQl[64 * 64];
    __shared__ __align__(16) __nv_bfloat16 sKh[64 * 64], sKl[64 * 64];
    __shared__ __align__(16) __nv_bfloat16 sVh[64 * 64], sVl[64 * 64];

    const int tid = threadIdx.x, lane = tid & 31, warp = tid >> 5;
    const int bh = blockIdx.y, n0 = blockIdx.x * 64;
    const size_t base = (size_t)bh * NNODE * HD;

    // stage Q tile (hi/lo) with swizzle
#pragma unroll
    for (int p = 0; p < 4; p++) {
        int s = tid + p * 128;
        int row = s >> 3, ch = s & 7, w = ch ^ (row & 7);
        size_t gi = base + (size_t)(n0 + row) * HD + ch * 8;
        *(uint4*)&sQh[row * 64 + w * 8] = *(const uint4*)&g_qh[gi];
        *(uint4*)&sQl[row * 64 + w * 8] = *(const uint4*)&g_ql[gi];
    }
    __syncthreads();

    const uint32_t baQh = smem_u32(sQh), baQl = smem_u32(sQl);
    const uint32_t baKh = smem_u32(sKh), baKl = smem_u32(sKl);
    const uint32_t baVh = smem_u32(sVh), baVl = smem_u32(sVl);

    uint32_t qh[4][4], ql[4][4];
#pragma unroll
    for (int kc = 0; kc < 4; kc++) {
        int row = warp * 16 + (lane & 15);
        int ch = (kc * 2 + (lane >> 4)) ^ (row & 7);
        ldmx4(qh[kc][0], qh[kc][1], qh[kc][2], qh[kc][3], baQh + row * 128 + ch * 16);
        ldmx4(ql[kc][0], ql[kc][1], ql[kc][2], ql[kc][3], baQl + row * 128 + ch * 16);
    }

    float o[8][4] = {};
    float mrow0 = -1e30f, mrow1 = -1e30f, lrow0 = 0.f, lrow1 = 0.f;
    const int g = lane >> 2, c = lane & 3;
    const float* bb0 = bias + ((size_t)bh << 20) + (size_t)(n0 + warp * 16 + g) * NNODE;

    for (int t = 0; t < 16; t++) {
        const int m0 = t * 64;
        __syncthreads();
#pragma unroll
        for (int p = 0; p < 4; p++) {
            int s = tid + p * 128;
            int row = s >> 3, ch = s & 7, w = ch ^ (row & 7);
            size_t gi = base + (size_t)(m0 + row) * HD + ch * 8;
            *(uint4*)&sKh[row * 64 + w * 8] = *(const uint4*)&g_kh[gi];
            *(uint4*)&sKl[row * 64 + w * 8] = *(const uint4*)&g_kl[gi];
            *(uint4*)&sVh[row * 64 + w * 8] = *(const uint4*)&g_vh[gi];
            *(uint4*)&sVl[row * 64 + w * 8] = *(const uint4*)&g_vl[gi];
        }
        __syncthreads();

        // S = Q K^T (3-pass split)
        float sfr[8][4] = {};
#pragma unroll
        for (int kc = 0; kc < 4; kc++) {
            uint32_t kbh[4][4], kbl[4][4];
#pragma unroll
            for (int pr = 0; pr < 4; pr++) {
                int row = pr * 16 + ((lane >> 4) << 3) + (lane & 7);
                int ch = (kc * 2 + ((lane >> 3) & 1)) ^ (row & 7);
                ldmx4(kbh[pr][0], kbh[pr][1], kbh[pr][2], kbh[pr][3], baKh + row * 128 + ch * 16);
                ldmx4(kbl[pr][0], kbl[pr][1], kbl[pr][2], kbl[pr][3], baKl + row * 128 + ch * 16);
            }
#pragma unroll
            for (int nt = 0; nt < 8; nt++) {
                uint32_t b0h = kbh[nt >> 1][(nt & 1) * 2], b1h = kbh[nt >> 1][(nt & 1) * 2 + 1];
                uint32_t b0l = kbl[nt >> 1][(nt & 1) * 2], b1l = kbl[nt >> 1][(nt & 1) * 2 + 1];
                mma16816(sfr[nt], qh[kc], b0h, b1h);
                mma16816(sfr[nt], qh[kc], b0l, b1l);
                mma16816(sfr[nt], ql[kc], b0h, b1h);
            }
        }

        // bias + online softmax (rows g and g+8)
        const float* bb = bb0 + m0;
        float mx0 = -1e30f, mx1 = -1e30f;
#pragma unroll
        for (int nt = 0; nt < 8; nt++) {
            float2 b01 = *(const float2*)(bb + nt * 8 + 2 * c);
            float2 b23 = *(const float2*)(bb + 8 * NNODE + nt * 8 + 2 * c);
            sfr[nt][0] += b01.x; sfr[nt][1] += b01.y;
            sfr[nt][2] += b23.x; sfr[nt][3] += b23.y;
            mx0 = fmaxf(mx0, fmaxf(sfr[nt][0], sfr[nt][1]));
            mx1 = fmaxf(mx1, fmaxf(sfr[nt][2], sfr[nt][3]));
        }
        mx0 = fmaxf(mx0, __shfl_xor_sync(0xffffffffu, mx0, 1));
        mx0 = fmaxf(mx0, __shfl_xor_sync(0xffffffffu, mx0, 2));
        mx1 = fmaxf(mx1, __shfl_xor_sync(0xffffffffu, mx1, 1));
        mx1 = fmaxf(mx1, __shfl_xor_sync(0xffffffffu, mx1, 2));
        float mn0 = fmaxf(mrow0, mx0), mn1 = fmaxf(mrow1, mx1);
        float al0 = __expf(mrow0 - mn0), al1 = __expf(mrow1 - mn1);
        mrow0 = mn0; mrow1 = mn1;
        float sum0 = 0.f, sum1 = 0.f;
#pragma unroll
        for (int nt = 0; nt < 8; nt++) {
            sfr[nt][0] = __expf(sfr[nt][0] - mn0);
            sfr[nt][1] = __expf(sfr[nt][1] - mn0);
            sfr[nt][2] = __expf(sfr[nt][2] - mn1);
            sfr[nt][3] = __expf(sfr[nt][3] - mn1);
            sum0 += sfr[nt][0] + sfr[nt][1];
            sum1 += sfr[nt][2] + sfr[nt][3];
        }
        sum0 += __shfl_xor_sync(0xffffffffu, sum0, 1);
        sum0 += __shfl_xor_sync(0xffffffffu, sum0, 2);
        sum1 += __shfl_xor_sync(0xffffffffu, sum1, 1);
        sum1 += __shfl_xor_sync(0xffffffffu, sum1, 2);
        lrow0 = lrow0 * al0 + sum0;
        lrow1 = lrow1 * al1 + sum1;
#pragma unroll
        for (int nt = 0; nt < 8; nt++) {
            o[nt][0] *= al0; o[nt][1] *= al0;
            o[nt][2] *= al1; o[nt][3] *= al1;
        }

        // O += P V (split P in registers, V via ldmatrix.trans)
#pragma unroll
        for (int kc = 0; kc < 4; kc++) {
            uint32_t pah[4], pal[4];
            {
                float p00 = sfr[2 * kc][0],     p01 = sfr[2 * kc][1];
                float p02 = sfr[2 * kc][2],     p03 = sfr[2 * kc][3];
                float p10 = sfr[2 * kc + 1][0], p11 = sfr[2 * kc + 1][1];
                float p12 = sfr[2 * kc + 1][2], p13 = sfr[2 * kc + 1][3];
                float hv;
                pah[0] = pack_bf16(p00, p01);
                hv = __bfloat162float(__float2bfloat16_rn(p00)); float r00 = p00 - hv;
                hv = __bfloat162float(__float2bfloat16_rn(p01)); float r01 = p01 - hv;
                pah[1] = pack_bf16(p02, p03);
                hv = __bfloat162float(__float2bfloat16_rn(p02)); float r02 = p02 - hv;
                hv = __bfloat162float(__float2bfloat16_rn(p03)); float r03 = p03 - hv;
                pah[2] = pack_bf16(p10, p11);
                hv = __bfloat162float(__float2bfloat16_rn(p10)); float r10 = p10 - hv;
                hv = __bfloat162float(__float2bfloat16_rn(p11)); float r11 = p11 - hv;
                pah[3] = pack_bf16(p12, p13);
                hv = __bfloat162float(__float2bfloat16_rn(p12)); float r12 = p12 - hv;
                hv = __bfloat162float(__float2bfloat16_rn(p13)); float r13 = p13 - hv;
                pal[0] = pack_bf16(r00, r01);
                pal[1] = pack_bf16(r02, r03);
                pal[2] = pack_bf16(r10, r11);
                pal[3] = pack_bf16(r12, r13);
            }
#pragma unroll
            for (int pr = 0; pr < 4; pr++) {
                int row = kc * 16 + ((lane >> 3) & 1) * 8 + (lane & 7);
                int ch = (2 * pr + (lane >> 4)) ^ (row & 7);
                uint32_t vh0, vh1, vh2, vh3, vl0, vl1, vl2, vl3;
                ldmx4t(vh0, vh1, vh2, vh3, baVh + row * 128 + ch * 16);
                ldmx4t(vl0, vl1, vl2, vl3, baVl + row * 128 + ch * 16);
                mma16816(o[2 * pr],     pah, vh0, vh1);
                mma16816(o[2 * pr],     pah, vl0, vl1);
                mma16816(o[2 * pr],     pal, vh0, vh1);
                mma16816(o[2 * pr + 1], pah, vh2, vh3);
                mma16816(o[2 * pr + 1], pah, vl2, vl3);
                mma16816(o[2 * pr + 1], pal, vh2, vh3);
            }
        }
    }

    // epilogue
    const float inv0 = 1.f / lrow0, inv1 = 1.f / lrow1;
    const int bg = bh / NH, hh = bh - bg * NH;
    const int r0g = n0 + warp * 16 + g;
#pragma unroll
    for (int nt = 0; nt < 8; nt++) {
        int d = nt * 8 + 2 * c;
        float2 v0 = make_float2(o[nt][0] * inv0, o[nt][1] * inv0);
        float2 v1 = make_float2(o[nt][2] * inv1, o[nt][3] * inv1);
        *(float2*)&g_attn[((size_t)r0g * NG + bg) * EDIM + hh * HD + d] = v0;
        *(float2*)&g_attn[((size_t)(r0g + 8) * NG + bg) * EDIM + hh * HD + d] = v1;
    }
}

// ---------------------------------------------------------------------------
// Kernel 3: out = attn @ W_out^T + b_out, masked (split-bf16 3-pass MMA)
// ---------------------------------------------------------------------------
__global__ __launch_bounds__(128) void out_gemm_kernel(
    const float* __restrict__ W, const float* __restrict__ bias,
    const void* __restrict__ maskp, float* __restrict__ out)
{
    __shared__ __align__(16) __nv_bfloat16 sAh[64 * 32], sAl[64 * 32];
    __shared__ __align__(16) __nv_bfloat16 sBh[64 * 32], sBl[64 * 32];
    const int tid = threadIdx.x, lane = tid & 31, warp = tid >> 5;
    const int wm = (warp >> 1) * 32, wn = (warp & 1) * 32;
    const int m0 = blockIdx.x * 64, n0 = blockIdx.y * 64;

    const uint32_t baAh = smem_u32(sAh), baAl = smem_u32(sAl);
    const uint32_t baBh = smem_u32(sBh), baBl = smem_u32(sBl);

    float acc[2][4][4] = {};

    for (int k0 = 0; k0 < EDIM; k0 += 32) {
#pragma unroll
        for (int p = 0; p < 2; p++) {
            int s = tid + p * 128;
            int row = s >> 2, sg = s & 3;
            int w = sg ^ (row & 3);
            float f[8];
            const float* ga = g_attn + (size_t)(m0 + row) * EDIM + k0 + sg * 8;
            *(float4*)f       = *(const float4*)ga;
            *(float4*)(f + 4) = *(const float4*)(ga + 4);
            uint4 h, l; split8(f, h, l);
            *(uint4*)&sAh[row * 32 + w * 8] = h;
            *(uint4*)&sAl[row * 32 + w * 8] = l;
            const float* gb = W + (size_t)(n0 + row) * EDIM + k0 + sg * 8;
            *(float4*)f       = *(const float4*)gb;
            *(float4*)(f + 4) = *(const float4*)(gb + 4);
            split8(f, h, l);
            *(uint4*)&sBh[row * 32 + w * 8] = h;
            *(uint4*)&sBl[row * 32 + w * 8] = l;
        }
        __syncthreads();
#pragma unroll
        for (int kc = 0; kc < 2; kc++) {
            uint32_t ah[2][4], al[2][4], bh[2][4], bl[2][4];
#pragma unroll
            for (int mt = 0; mt < 2; mt++) {
                int row = wm + mt * 16 + (lane & 15);
                int ch = (kc * 2 + (lane >> 4)) ^ (row & 3);
                ldmx4(ah[mt][0], ah[mt][1], ah[mt][2], ah[mt][3], baAh + row * 64 + ch * 16);
                ldmx4(al[mt][0], al[mt][1], al[mt][2], al[mt][3], baAl + row * 64 + ch * 16);
            }
#pragma unroll
            for (int pr = 0; pr < 2; pr++) {
                int row = wn + pr * 16 + ((lane >> 4) << 3) + (lane & 7);
                int ch = (kc * 2 + ((lane >> 3) & 1)) ^ (row & 3);
                ldmx4(bh[pr][0], bh[pr][1], bh[pr][2], bh[pr][3], baBh + row * 64 + ch * 16);
                ldmx4(bl[pr][0], bl[pr][1], bl[pr][2], bl[pr][3], baBl + row * 64 + ch * 16);
            }
#pragma unroll
            for (int mt = 0; mt < 2; mt++)
#pragma unroll
                for (int nt = 0; nt < 4; nt++) {
                    uint32_t b0h = bh[nt >> 1][(nt & 1) * 2], b1h = bh[nt >> 1][(nt & 1) * 2 + 1];
                    uint32_t b0l = bl[nt >> 1][(nt & 1) * 2], b1l = bl[nt >> 1][(nt & 1) * 2 + 1];
                    mma16816(acc[mt][nt], ah[mt], b0h, b1h);
                    mma16816(acc[mt][nt], ah[mt], b0l, b1l);
                    mma16816(acc[mt][nt], al[mt], b0h, b1h);
                }
        }
        __syncthreads();
    }

    const int g = lane >> 2, c = lane & 3;
    const int mkind = g_mask_kind;
#pragma unroll
    for (int mt = 0; mt < 2; mt++)
#pragma unroll
        for (int rr = 0; rr < 2; rr++) {
            int row = m0 + wm + mt * 16 + g + rr * 8;
            int node = row >> 2, bg = row & 3;
            int midx = bg * NNODE + node;
            bool keep;
            if (mkind == 1)      keep = ((const int*)maskp)[midx] != 0;
            else if (mkind == 2) keep = ((const float*)maskp)[midx] != 0.0f;
            else                 keep = ((const uint8_t*)maskp)[midx] != 0;
#pragma unroll
            for (int nt = 0; nt < 4; nt++) {
                int col = n0 + wn + nt * 8 + 2 * c;
                float v0 = keep ? (acc[mt][nt][rr * 2 + 0] + bias[col])     : 0.0f;
                float v1 = keep ? (acc[mt][nt][rr * 2 + 1] + bias[col + 1]) : 0.0f;
                *(float2*)&out[(size_t)row * EDIM + col] = make_float2(v0, v1);
            }
        }
}

// ---------------------------------------------------------------------------
extern "C" void kernel_launch(void* const* d_in, const int* in_sizes, int n_in,
                              void* d_out, int out_size) {
    const float* query     = (const float*)d_in[0];
    const float* attn_bias = (const float*)d_in[1];
    const void*  mask      = d_in[2];
    const float* W_in      = (const float*)d_in[3];
    const float* b_in      = (const float*)d_in[4];
    const float* W_out     = (const float*)d_in[5];
    const float* b_out     = (const float*)d_in[6];
    float* out = (float*)d_out;

    detect_mask_kernel<<<1, 256>>>((const uint8_t*)mask);
    qkv_gemm_kernel<<<dim3(64, 36), 128>>>(query, W_in, b_in);
    attn_kernel<<<dim3(16, BHD), 128>>>(attn_bias);
    out_gemm_kernel<<<dim3(64, 12), 128>>>(W_out, b_out, mask, out);
}

// round 3
// speedup vs baseline: 3.0843x; 1.4854x over previous
#include <cuda_runtime.h>
#include <cuda_bf16.h>
#include <cstdint>

#define NG    4
#define NH    12
#define BHD   48
#define NNODE 1024
#define EDIM  768
#define HD    64
#define QSCALE 0.125f
#define MROWS 4096

typedef __nv_bfloat16 bf16;

// ---------------- scratch (no cudaMalloc allowed) ----------------
__device__ bf16 g_qxh[MROWS * EDIM],   g_qxl[MROWS * EDIM];     // split query
__device__ bf16 g_wih[3 * EDIM * EDIM], g_wil[3 * EDIM * EDIM]; // split W_in
__device__ bf16 g_woh[EDIM * EDIM],     g_wol[EDIM * EDIM];     // split W_out
__device__ bf16 g_qh[BHD * NNODE * HD], g_ql[BHD * NNODE * HD];
__device__ bf16 g_kh[BHD * NNODE * HD], g_kl[BHD * NNODE * HD];
__device__ bf16 g_vh[BHD * NNODE * HD], g_vl[BHD * NNODE * HD];
__device__ bf16 g_ah[MROWS * EDIM],     g_al[MROWS * EDIM];     // split attn out
__device__ int  g_mask_kind;

// ---------------- helpers ----------------
__device__ __forceinline__ uint32_t smem_u32(const void* p) {
    return (uint32_t)__cvta_generic_to_shared(p);
}
__device__ __forceinline__ void cp16(uint32_t dst, const void* src) {
    asm volatile("cp.async.cg.shared.global [%0],[%1],16;\n" :: "r"(dst), "l"(src) : "memory");
}
__device__ __forceinline__ void cpcommit() {
    asm volatile("cp.async.commit_group;\n" ::: "memory");
}
template<int N> __device__ __forceinline__ void cpwait() {
    asm volatile("cp.async.wait_group %0;\n" :: "n"(N) : "memory");
}
__device__ __forceinline__ void ldmx4(uint32_t& r0, uint32_t& r1, uint32_t& r2, uint32_t& r3, uint32_t a) {
    asm volatile("ldmatrix.sync.aligned.m8n8.x4.shared.b16 {%0,%1,%2,%3},[%4];\n"
                 : "=r"(r0), "=r"(r1), "=r"(r2), "=r"(r3) : "r"(a));
}
__device__ __forceinline__ void ldmx4t(uint32_t& r0, uint32_t& r1, uint32_t& r2, uint32_t& r3, uint32_t a) {
    asm volatile("ldmatrix.sync.aligned.m8n8.x4.trans.shared.b16 {%0,%1,%2,%3},[%4];\n"
                 : "=r"(r0), "=r"(r1), "=r"(r2), "=r"(r3) : "r"(a));
}
__device__ __forceinline__ void mma16816(float* c, const uint32_t* a, uint32_t b0, uint32_t b1) {
    asm volatile("mma.sync.aligned.m16n8k16.row.col.f32.bf16.bf16.f32 "
                 "{%0,%1,%2,%3},{%4,%5,%6,%7},{%8,%9},{%0,%1,%2,%3};\n"
                 : "+f"(c[0]), "+f"(c[1]), "+f"(c[2]), "+f"(c[3])
                 : "r"(a[0]), "r"(a[1]), "r"(a[2]), "r"(a[3]), "r"(b0), "r"(b1));
}
__device__ __forceinline__ uint32_t pack_bf16(float x, float y) {
    bf16 bx = __float2bfloat16_rn(x), by = __float2bfloat16_rn(y);
    uint16_t ux = *reinterpret_cast<uint16_t*>(&bx);
    uint16_t uy = *reinterpret_cast<uint16_t*>(&by);
    return (uint32_t)ux | ((uint32_t)uy << 16);
}
__device__ __forceinline__ void split2(float v0, float v1, uint32_t& h, uint32_t& l) {
    bf16 b0 = __float2bfloat16_rn(v0), b1 = __float2bfloat16_rn(v1);
    float l0 = v0 - __bfloat162float(b0);
    float l1 = v1 - __bfloat162float(b1);
    uint16_t u0 = *reinterpret_cast<uint16_t*>(&b0);
    uint16_t u1 = *reinterpret_cast<uint16_t*>(&b1);
    h = (uint32_t)u0 | ((uint32_t)u1 << 16);
    l = pack_bf16(l0, l1);
}

// ---------------- mask dtype probe ----------------
__global__ void detect_mask_kernel(const uint8_t* __restrict__ m) {
    __shared__ int or_b0, or_b123;
    if (threadIdx.x == 0) { or_b0 = 0; or_b123 = 0; }
    __syncthreads();
    int a0 = 0, a123 = 0;
    for (int w = threadIdx.x; w < 1024; w += blockDim.x) {
        a0   |= m[4 * w];
        a123 |= m[4 * w + 1] | m[4 * w + 2] | m[4 * w + 3];
    }
    if (a0)   atomicOr(&or_b0, 1);
    if (a123) atomicOr(&or_b123, 1);
    __syncthreads();
    if (threadIdx.x == 0) {
        if (or_b0 == 0)        g_mask_kind = 2;
        else if (or_b123 == 0) g_mask_kind = 1;
        else                   g_mask_kind = 0;
    }
}

// ---------------- fp32 -> bf16 hi/lo pre-split ----------------
__global__ void split_kernel(const float4* __restrict__ src, int which, int n4) {
    uint2* h; uint2* l;
    if (which == 0)      { h = (uint2*)g_qxh; l = (uint2*)g_qxl; }
    else if (which == 1) { h = (uint2*)g_wih; l = (uint2*)g_wil; }
    else                 { h = (uint2*)g_woh; l = (uint2*)g_wol; }
    for (int i = blockIdx.x * blockDim.x + threadIdx.x; i < n4; i += gridDim.x * blockDim.x) {
        float4 f = src[i];
        uint32_t h0, l0, h1, l1;
        split2(f.x, f.y, h0, l0);
        split2(f.z, f.w, h1, l1);
        h[i] = make_uint2(h0, h1);
        l[i] = make_uint2(l0, l1);
    }
}

// ============================================================================
// GEMM core: BM=128, BN=64, BK=32, 256 threads (8 warps, 4x2), warp 32x32.
// 2-stage cp.async pipeline; inputs are pre-split bf16 hi/lo.
// ============================================================================
#define STG_BYTES 24576   // Ah 8192 + Al 8192 + Bh 4096 + Bl 4096

__device__ __forceinline__ void gemm_load_stage(
    uint32_t sbase, const bf16* Ah, const bf16* Al, const bf16* Bh, const bf16* Bl,
    int m0, int n0, int k0, int tid)
{
    uint32_t aH = sbase, aL = sbase + 8192, bH = sbase + 16384, bL = sbase + 20480;
#pragma unroll
    for (int it = 0; it < 2; it++) {
        int s = tid + it * 256;
        int row = s >> 2, sg = s & 3;
        uint32_t off = (uint32_t)(row * 64 + ((sg ^ (row & 3)) * 16));
        size_t gi = (size_t)(m0 + row) * EDIM + k0 + sg * 8;
        cp16(aH + off, Ah + gi);
        cp16(aL + off, Al + gi);
    }
    {
        int s = tid;
        int row = s >> 2, sg = s & 3;
        uint32_t off = (uint32_t)(row * 64 + ((sg ^ (row & 3)) * 16));
        size_t gi = (size_t)(n0 + row) * EDIM + k0 + sg * 8;
        cp16(bH + off, Bh + gi);
        cp16(bL + off, Bl + gi);
    }
}

__device__ __forceinline__ void gemm_compute_stage(
    uint32_t sbase, int lane, int wm, int wn, float acc[2][4][4])
{
    uint32_t aH = sbase, aL = sbase + 8192, bH = sbase + 16384, bL = sbase + 20480;
#pragma unroll
    for (int kc = 0; kc < 2; kc++) {
        uint32_t ah[2][4], al[2][4], bh[2][4], bl[2][4];
#pragma unroll
        for (int mt = 0; mt < 2; mt++) {
            int row = wm + mt * 16 + (lane & 15);
            int ch = (kc * 2 + (lane >> 4)) ^ (row & 3);
            ldmx4(ah[mt][0], ah[mt][1], ah[mt][2], ah[mt][3], aH + row * 64 + ch * 16);
            ldmx4(al[mt][0], al[mt][1], al[mt][2], al[mt][3], aL + row * 64 + ch * 16);
        }
#pragma unroll
        for (int pr = 0; pr < 2; pr++) {
            int row = wn + pr * 16 + ((lane >> 4) << 3) + (lane & 7);
            int ch = (kc * 2 + ((lane >> 3) & 1)) ^ (row & 3);
            ldmx4(bh[pr][0], bh[pr][1], bh[pr][2], bh[pr][3], bH + row * 64 + ch * 16);
            ldmx4(bl[pr][0], bl[pr][1], bl[pr][2], bl[pr][3], bL + row * 64 + ch * 16);
        }
#pragma unroll
        for (int mt = 0; mt < 2; mt++)
#pragma unroll
            for (int nt = 0; nt < 4; nt++) {
                uint32_t b0h = bh[nt >> 1][(nt & 1) * 2], b1h = bh[nt >> 1][(nt & 1) * 2 + 1];
                uint32_t b0l = bl[nt >> 1][(nt & 1) * 2], b1l = bl[nt >> 1][(nt & 1) * 2 + 1];
                mma16816(acc[mt][nt], ah[mt], b0h, b1h);
                mma16816(acc[mt][nt], ah[mt], b0l, b1l);
                mma16816(acc[mt][nt], al[mt], b0h, b1h);
            }
    }
}

#define GEMM_PIPE(AH, AL, BH, BL)                                             \
    extern __shared__ __align__(16) char dynsm[];                             \
    const int tid = threadIdx.x, lane = tid & 31, warp = tid >> 5;            \
    const int wm = (warp >> 1) * 32, wn = (warp & 1) * 32;                    \
    const int m0 = blockIdx.x * 128, n0 = blockIdx.y * 64;                    \
    const uint32_t sb0 = smem_u32(dynsm), sb1 = sb0 + STG_BYTES;              \
    float acc[2][4][4] = {};                                                  \
    gemm_load_stage(sb0, AH, AL, BH, BL, m0, n0, 0, tid);                     \
    cpcommit();                                                               \
    for (int kt = 0; kt < 24; kt++) {                                         \
        if (kt < 23) {                                                        \
            gemm_load_stage((kt & 1) ? sb0 : sb1, AH, AL, BH, BL,             \
                            m0, n0, (kt + 1) * 32, tid);                      \
            cpcommit();                                                       \
            cpwait<1>();                                                      \
        } else cpwait<0>();                                                   \
        __syncthreads();                                                      \
        gemm_compute_stage((kt & 1) ? sb1 : sb0, lane, wm, wn, acc);          \
        __syncthreads();                                                      \
    }

// ---------------------------------------------------------------------------
// Kernel 1: qkv projection. Grid (32, 36).
// ---------------------------------------------------------------------------
__global__ __launch_bounds__(256) void qkv_gemm_kernel(const float* __restrict__ bias)
{
    GEMM_PIPE(g_qxh, g_qxl, g_wih, g_wil)

    const int g = lane >> 2, c = lane & 3;
    const int sec = blockIdx.y / 12, hh = blockIdx.y % 12;
    bf16 *dh, *dl;
    if (sec == 0)      { dh = g_qh; dl = g_ql; }
    else if (sec == 1) { dh = g_kh; dl = g_kl; }
    else               { dh = g_vh; dl = g_vl; }

#pragma unroll
    for (int mt = 0; mt < 2; mt++)
#pragma unroll
        for (int nt = 0; nt < 4; nt++) {
            int dloc = wn + nt * 8 + 2 * c;
            float bv0 = bias[n0 + dloc], bv1 = bias[n0 + dloc + 1];
#pragma unroll
            for (int rr = 0; rr < 2; rr++) {
                int row = m0 + wm + mt * 16 + g + rr * 8;
                int node = row >> 2, bg = row & 3;
                float v0 = acc[mt][nt][rr * 2 + 0] + bv0;
                float v1 = acc[mt][nt][rr * 2 + 1] + bv1;
                if (sec == 0) { v0 *= QSCALE; v1 *= QSCALE; }
                uint32_t ph, pl;
                split2(v0, v1, ph, pl);
                size_t idx = (((size_t)(bg * NH + hh) * NNODE + node) * HD + dloc);
                *(uint32_t*)&dh[idx] = ph;
                *(uint32_t*)&dl[idx] = pl;
            }
        }
}

// ---------------------------------------------------------------------------
// Kernel 3: out projection + mask. Grid (32, 12).
// ---------------------------------------------------------------------------
__global__ __launch_bounds__(256) void out_gemm_kernel(
    const float* __restrict__ bias, const void* __restrict__ maskp,
    float* __restrict__ out)
{
    GEMM_PIPE(g_ah, g_al, g_woh, g_wol)

    const int g = lane >> 2, c = lane & 3;
    const int mkind = g_mask_kind;
#pragma unroll
    for (int mt = 0; mt < 2; mt++)
#pragma unroll
        for (int rr = 0; rr < 2; rr++) {
            int row = m0 + wm + mt * 16 + g + rr * 8;
            int node = row >> 2, bg = row & 3;
            int midx = bg * NNODE + node;
            bool keep;
            if (mkind == 1)      keep = ((const int*)maskp)[midx] != 0;
            else if (mkind == 2) keep = ((const float*)maskp)[midx] != 0.0f;
            else                 keep = ((const uint8_t*)maskp)[midx] != 0;
#pragma unroll
            for (int nt = 0; nt < 4; nt++) {
                int col = n0 + wn + nt * 8 + 2 * c;
                float v0 = keep ? (acc[mt][nt][rr * 2 + 0] + bias[col])     : 0.0f;
                float v1 = keep ? (acc[mt][nt][rr * 2 + 1] + bias[col + 1]) : 0.0f;
                *(float2*)&out[(size_t)row * EDIM + col] = make_float2(v0, v1);
            }
        }
}

// ============================================================================
// Kernel 2: flash attention. CTA = 64 q-rows x 1 head, 4 warps.
// 32-key double-buffered cp.async stages; bias tile staged in smem too.
// ============================================================================
#define ASTG_BYTES 25600          // Kh 4096 Kl 4096 Vh 4096 Vl 4096 bias 9216
#define BIAS_PITCH 36             // floats per bias row in smem

__device__ __forceinline__ void attn_load_stage(
    uint32_t sbase, size_t kvbase, const float* bb, int m0, int n0, int tid)
{
    uint32_t kH = sbase, kL = sbase + 4096, vH = sbase + 8192, vL = sbase + 12288;
    uint32_t bS = sbase + 16384;
#pragma unroll
    for (int it = 0; it < 2; it++) {
        int s = tid + it * 128;
        int row = s >> 3, ch = s & 7;
        uint32_t off = (uint32_t)(row * 128 + ((ch ^ (row & 7)) * 16));
        size_t gi = kvbase + (size_t)(m0 + row) * HD + ch * 8;
        cp16(kH + off, g_kh + gi);
        cp16(kL + off, g_kl + gi);
        cp16(vH + off, g_vh + gi);
        cp16(vL + off, g_vl + gi);
    }
#pragma unroll
    for (int it = 0; it < 4; it++) {
        int s = tid + it * 128;
        int row = s >> 3, ch = s & 7;           // 64 rows x 8 chunks (32 floats)
        cp16(bS + (uint32_t)(row * (BIAS_PITCH * 4) + ch * 16),
             bb + (size_t)(n0 + row) * NNODE + m0 + ch * 4);
    }
}

__global__ __launch_bounds__(128) void attn_kernel(const float* __restrict__ bias)
{
    extern __shared__ __align__(16) char dynsm[];
    const int tid = threadIdx.x, lane = tid & 31, warp = tid >> 5;
    const int bh = blockIdx.y, n0 = blockIdx.x * 64;
    const size_t base = (size_t)bh * NNODE * HD;
    const float* bb = bias + ((size_t)bh << 20);

    const uint32_t qH = smem_u32(dynsm), qL = qH + 8192;
    const uint32_t st0 = qH + 16384, st1 = st0 + ASTG_BYTES;

    // prologue: Q group, then stage 0
#pragma unroll
    for (int it = 0; it < 4; it++) {
        int s = tid + it * 128;
        int row = s >> 3, ch = s & 7;
        uint32_t off = (uint32_t)(row * 128 + ((ch ^ (row & 7)) * 16));
        size_t gi = base + (size_t)(n0 + row) * HD + ch * 8;
        cp16(qH + off, g_qh + gi);
        cp16(qL + off, g_ql + gi);
    }
    cpcommit();
    attn_load_stage(st0, base, bb, 0, n0, tid);
    cpcommit();

    cpwait<1>();      // Q ready
    __syncthreads();

    uint32_t qh[4][4], ql[4][4];
#pragma unroll
    for (int kc = 0; kc < 4; kc++) {
        int row = warp * 16 + (lane & 15);
        int ch = (kc * 2 + (lane >> 4)) ^ (row & 7);
        ldmx4(qh[kc][0], qh[kc][1], qh[kc][2], qh[kc][3], qH + row * 128 + ch * 16);
        ldmx4(ql[kc][0], ql[kc][1], ql[kc][2], ql[kc][3], qL + row * 128 + ch * 16);
    }

    float o[8][4] = {};
    float mrow0 = -1e30f, mrow1 = -1e30f, lrow0 = 0.f, lrow1 = 0.f;
    const int g = lane >> 2, c = lane & 3;

    for (int t = 0; t < 32; t++) {
        uint32_t cur = (t & 1) ? st1 : st0;
        if (t < 31) {
            attn_load_stage((t & 1) ? st0 : st1, base, bb, (t + 1) * 32, n0, tid);
            cpcommit();
            cpwait<1>();
        } else cpwait<0>();
        __syncthreads();

        uint32_t kH = cur, kL = cur + 4096, vH = cur + 8192, vL = cur + 12288;
        const float* bsm = (const float*)(dynsm + (cur - qH) + 16384);

        // S = Q K^T over 32 keys
        float sfr[4][4] = {};
#pragma unroll
        for (int kc = 0; kc < 4; kc++) {
            uint32_t kbh[2][4], kbl[2][4];
#pragma unroll
            for (int pr = 0; pr < 2; pr++) {
                int row = pr * 16 + ((lane >> 4) << 3) + (lane & 7);
                int ch = (kc * 2 + ((lane >> 3) & 1)) ^ (row & 7);
                ldmx4(kbh[pr][0], kbh[pr][1], kbh[pr][2], kbh[pr][3], kH + row * 128 + ch * 16);
                ldmx4(kbl[pr][0], kbl[pr][1], kbl[pr][2], kbl[pr][3], kL + row * 128 + ch * 16);
            }
#pragma unroll
            for (int nt = 0; nt < 4; nt++) {
                uint32_t b0h = kbh[nt >> 1][(nt & 1) * 2], b1h = kbh[nt >> 1][(nt & 1) * 2 + 1];
                uint32_t b0l = kbl[nt >> 1][(nt & 1) * 2], b1l = kbl[nt >> 1][(nt & 1) * 2 + 1];
                mma16816(sfr[nt], qh[kc], b0h, b1h);
                mma16816(sfr[nt], qh[kc], b0l, b1l);
                mma16816(sfr[nt], ql[kc], b0h, b1h);
            }
        }

        // bias (from smem) + online softmax
        float mx0 = -1e30f, mx1 = -1e30f;
#pragma unroll
        for (int nt = 0; nt < 4; nt++) {
            int col = nt * 8 + 2 * c;
            float2 b01 = *(const float2*)(bsm + (warp * 16 + g) * BIAS_PITCH + col);
            float2 b23 = *(const float2*)(bsm + (warp * 16 + g + 8) * BIAS_PITCH + col);
            sfr[nt][0] += b01.x; sfr[nt][1] += b01.y;
            sfr[nt][2] += b23.x; sfr[nt][3] += b23.y;
            mx0 = fmaxf(mx0, fmaxf(sfr[nt][0], sfr[nt][1]));
            mx1 = fmaxf(mx1, fmaxf(sfr[nt][2], sfr[nt][3]));
        }
        mx0 = fmaxf(mx0, __shfl_xor_sync(0xffffffffu, mx0, 1));
        mx0 = fmaxf(mx0, __shfl_xor_sync(0xffffffffu, mx0, 2));
        mx1 = fmaxf(mx1, __shfl_xor_sync(0xffffffffu, mx1, 1));
        mx1 = fmaxf(mx1, __shfl_xor_sync(0xffffffffu, mx1, 2));
        float mn0 = fmaxf(mrow0, mx0), mn1 = fmaxf(mrow1, mx1);
        float al0 = __expf(mrow0 - mn0), al1 = __expf(mrow1 - mn1);
        mrow0 = mn0; mrow1 = mn1;
        float sum0 = 0.f, sum1 = 0.f;
#pragma unroll
        for (int nt = 0; nt < 4; nt++) {
            sfr[nt][0] = __expf(sfr[nt][0] - mn0);
            sfr[nt][1] = __expf(sfr[nt][1] - mn0);
            sfr[nt][2] = __expf(sfr[nt][2] - mn1);
            sfr[nt][3] = __expf(sfr[nt][3] - mn1);
            sum0 += sfr[nt][0] + sfr[nt][1];
            sum1 += sfr[nt][2] + sfr[nt][3];
        }
        sum0 += __shfl_xor_sync(0xffffffffu, sum0, 1);
        sum0 += __shfl_xor_sync(0xffffffffu, sum0, 2);
        sum1 += __shfl_xor_sync(0xffffffffu, sum1, 1);
        sum1 += __shfl_xor_sync(0xffffffffu, sum1, 2);
        lrow0 = lrow0 * al0 + sum0;
        lrow1 = lrow1 * al1 + sum1;
#pragma unroll
        for (int nt = 0; nt < 8; nt++) {
            o[nt][0] *= al0; o[nt][1] *= al0;
            o[nt][2] *= al1; o[nt][3] *= al1;
        }

        // O += P V
#pragma unroll
        for (int kc = 0; kc < 2; kc++) {
            uint32_t pah[4], pal[4];
            split2(sfr[2 * kc][0],     sfr[2 * kc][1],     pah[0], pal[0]);
            split2(sfr[2 * kc][2],     sfr[2 * kc][3],     pah[1], pal[1]);
            split2(sfr[2 * kc + 1][0], sfr[2 * kc + 1][1], pah[2], pal[2]);
            split2(sfr[2 * kc + 1][2], sfr[2 * kc + 1][3], pah[3], pal[3]);
#pragma unroll
            for (int pr = 0; pr < 4; pr++) {
                int row = kc * 16 + ((lane >> 3) & 1) * 8 + (lane & 7);
                int ch = (2 * pr + (lane >> 4)) ^ (row & 7);
                uint32_t vh0, vh1, vh2, vh3, vl0, vl1, vl2, vl3;
                ldmx4t(vh0, vh1, vh2, vh3, vH + row * 128 + ch * 16);
                ldmx4t(vl0, vl1, vl2, vl3, vL + row * 128 + ch * 16);
                mma16816(o[2 * pr],     pah, vh0, vh1);
                mma16816(o[2 * pr],     pah, vl0, vl1);
                mma16816(o[2 * pr],     pal, vh0, vh1);
                mma16816(o[2 * pr + 1], pah, vh2, vh3);
                mma16816(o[2 * pr + 1], pah, vl2, vl3);
                mma16816(o[2 * pr + 1], pal, vh2, vh3);
            }
        }
        __syncthreads();
    }

    // epilogue: normalize, split to bf16 hi/lo, store [N, B, E]
    const float inv0 = 1.f / lrow0, inv1 = 1.f / lrow1;
    const int bg = bh / NH, hh = bh - bg * NH;
    const int r0g = n0 + warp * 16 + g;
#pragma unroll
    for (int nt = 0; nt < 8; nt++) {
        int d = nt * 8 + 2 * c;
        uint32_t ph, pl;
        size_t i0 = ((size_t)r0g * NG + bg) * EDIM + hh * HD + d;
        size_t i1 = ((size_t)(r0g + 8) * NG + bg) * EDIM + hh * HD + d;
        split2(o[nt][0] * inv0, o[nt][1] * inv0, ph, pl);
        *(uint32_t*)&g_ah[i0] = ph; *(uint32_t*)&g_al[i0] = pl;
        split2(o[nt][2] * inv1, o[nt][3] * inv1, ph, pl);
        *(uint32_t*)&g_ah[i1] = ph; *(uint32_t*)&g_al[i1] = pl;
    }
}

// ---------------------------------------------------------------------------
extern "C" void kernel_launch(void* const* d_in, const int* in_sizes, int n_in,
                              void* d_out, int out_size) {
    const float* query     = (const float*)d_in[0];
    const float* attn_bias = (const float*)d_in[1];
    const void*  mask      = d_in[2];
    const float* W_in      = (const float*)d_in[3];
    const float* b_in      = (const float*)d_in[4];
    const float* W_out     = (const float*)d_in[5];
    const float* b_out     = (const float*)d_in[6];
    float* out = (float*)d_out;

    detect_mask_kernel<<<1, 256>>>((const uint8_t*)mask);
    split_kernel<<<1184, 256>>>((const float4*)query, 0, MROWS * EDIM / 4);
    split_kernel<<<1184, 256>>>((const float4*)W_in,  1, 3 * EDIM * EDIM / 4);
    split_kernel<<<592,  256>>>((const float4*)W_out, 2, EDIM * EDIM / 4);

    const int gsm = 2 * STG_BYTES;  // 48 KB
    cudaFuncSetAttribute((const void*)qkv_gemm_kernel,
                         cudaFuncAttributeMaxDynamicSharedMemorySize, gsm);
    cudaFuncSetAttribute((const void*)out_gemm_kernel,
                         cudaFuncAttributeMaxDynamicSharedMemorySize, gsm);
    qkv_gemm_kernel<<<dim3(32, 36), 256, gsm>>>(b_in);

    const int asm_bytes = 16384 + 2 * ASTG_BYTES;  // 67584
    cudaFuncSetAttribute((const void*)attn_kernel,
                         cudaFuncAttributeMaxDynamicSharedMemorySize, asm_bytes);
    attn_kernel<<<dim3(16, BHD), 128, asm_bytes>>>(attn_bias);

    out_gemm_kernel<<<dim3(32, 12), 256, gsm>>>(b_out, mask, out);
}

// round 4
// speedup vs baseline: 3.9523x; 1.2814x over previous
#include <cuda_runtime.h>
#include <cuda_fp16.h>
#include <cstdint>

#define NG    4
#define NH    12
#define BHD   48
#define NNODE 1024
#define EDIM  768
#define HD    64
#define QSCALE 0.125f
#define MROWS 4096

// ---------------- scratch (no cudaMalloc allowed) ----------------
__device__ __half g_qxh[MROWS * EDIM];                           // query rounded fp16
__device__ __half g_wih[3 * EDIM * EDIM], g_wil[3 * EDIM * EDIM];// W_in hi/lo
__device__ __half g_woh[EDIM * EDIM],     g_wol[EDIM * EDIM];    // W_out hi/lo
__device__ __half g_qh[BHD * NNODE * HD];                        // q rounded (scaled)
__device__ __half g_kh[BHD * NNODE * HD], g_kl[BHD * NNODE * HD];
__device__ __half g_vh[BHD * NNODE * HD], g_vl[BHD * NNODE * HD];
__device__ __half g_ah[MROWS * EDIM];                            // attn out rounded
__device__ int    g_mask_kind;

// ---------------- helpers ----------------
__device__ __forceinline__ uint32_t smem_u32(const void* p) {
    return (uint32_t)__cvta_generic_to_shared(p);
}
__device__ __forceinline__ void cp16(uint32_t dst, const void* src) {
    asm volatile("cp.async.cg.shared.global [%0],[%1],16;\n" :: "r"(dst), "l"(src) : "memory");
}
__device__ __forceinline__ void cpcommit() {
    asm volatile("cp.async.commit_group;\n" ::: "memory");
}
template<int N> __device__ __forceinline__ void cpwait() {
    asm volatile("cp.async.wait_group %0;\n" :: "n"(N) : "memory");
}
__device__ __forceinline__ void ldmx4(uint32_t& r0, uint32_t& r1, uint32_t& r2, uint32_t& r3, uint32_t a) {
    asm volatile("ldmatrix.sync.aligned.m8n8.x4.shared.b16 {%0,%1,%2,%3},[%4];\n"
                 : "=r"(r0), "=r"(r1), "=r"(r2), "=r"(r3) : "r"(a));
}
__device__ __forceinline__ void ldmx4t(uint32_t& r0, uint32_t& r1, uint32_t& r2, uint32_t& r3, uint32_t a) {
    asm volatile("ldmatrix.sync.aligned.m8n8.x4.trans.shared.b16 {%0,%1,%2,%3},[%4];\n"
                 : "=r"(r0), "=r"(r1), "=r"(r2), "=r"(r3) : "r"(a));
}
__device__ __forceinline__ void mma16816(float* c, const uint32_t* a, uint32_t b0, uint32_t b1) {
    asm volatile("mma.sync.aligned.m16n8k16.row.col.f32.f16.f16.f32 "
                 "{%0,%1,%2,%3},{%4,%5,%6,%7},{%8,%9},{%0,%1,%2,%3};\n"
                 : "+f"(c[0]), "+f"(c[1]), "+f"(c[2]), "+f"(c[3])
                 : "r"(a[0]), "r"(a[1]), "r"(a[2]), "r"(a[3]), "r"(b0), "r"(b1));
}
__device__ __forceinline__ uint32_t pack_half2(float x, float y) {
    __half2 h = __floats2half2_rn(x, y);
    return *reinterpret_cast<uint32_t*>(&h);
}
__device__ __forceinline__ void split2h(float v0, float v1, uint32_t& h, uint32_t& l) {
    __half b0 = __float2half_rn(v0), b1 = __float2half_rn(v1);
    float l0 = v0 - __half2float(b0);
    float l1 = v1 - __half2float(b1);
    uint16_t u0 = *reinterpret_cast<uint16_t*>(&b0);
    uint16_t u1 = *reinterpret_cast<uint16_t*>(&b1);
    h = (uint32_t)u0 | ((uint32_t)u1 << 16);
    l = pack_half2(l0, l1);
}

// ---------------- mask dtype probe ----------------
__global__ void detect_mask_kernel(const uint8_t* __restrict__ m) {
    __shared__ int or_b0, or_b123;
    if (threadIdx.x == 0) { or_b0 = 0; or_b123 = 0; }
    __syncthreads();
    int a0 = 0, a123 = 0;
    for (int w = threadIdx.x; w < 1024; w += blockDim.x) {
        a0   |= m[4 * w];
        a123 |= m[4 * w + 1] | m[4 * w + 2] | m[4 * w + 3];
    }
    if (a0)   atomicOr(&or_b0, 1);
    if (a123) atomicOr(&or_b123, 1);
    __syncthreads();
    if (threadIdx.x == 0) {
        if (or_b0 == 0)        g_mask_kind = 2;
        else if (or_b123 == 0) g_mask_kind = 1;
        else                   g_mask_kind = 0;
    }
}

// ---------------- prep: query rounded, weights split ----------------
__global__ void split_q_kernel(const float4* __restrict__ src, int n4) {
    uint2* h = (uint2*)g_qxh;
    for (int i = blockIdx.x * blockDim.x + threadIdx.x; i < n4; i += gridDim.x * blockDim.x) {
        float4 f = src[i];
        h[i] = make_uint2(pack_half2(f.x, f.y), pack_half2(f.z, f.w));
    }
}
__global__ void split_w_kernel(const float4* __restrict__ src, int which, int n4) {
    uint2* h; uint2* l;
    if (which == 1) { h = (uint2*)g_wih; l = (uint2*)g_wil; }
    else            { h = (uint2*)g_woh; l = (uint2*)g_wol; }
    for (int i = blockIdx.x * blockDim.x + threadIdx.x; i < n4; i += gridDim.x * blockDim.x) {
        float4 f = src[i];
        uint32_t h0, l0, h1, l1;
        split2h(f.x, f.y, h0, l0);
        split2h(f.z, f.w, h1, l1);
        h[i] = make_uint2(h0, h1);
        l[i] = make_uint2(l0, l1);
    }
}

// ============================================================================
// GEMM core: BM=128, BN=64, BK=32, 256 threads (8 warps, 4x2), warp 32x32.
// A rounded fp16, B split hi/lo. 3-stage cp.async, one barrier per k-iter.
// ============================================================================
#define GSTG 16384   // Ah 8192 + Bh 4096 + Bl 4096

__device__ __forceinline__ void gemm_load_stage(
    uint32_t sbase, const __half* A, const __half* Bh, const __half* Bl,
    int m0, int n0, int k0, int tid)
{
    uint32_t aH = sbase, bH = sbase + 8192, bL = sbase + 12288;
#pragma unroll
    for (int it = 0; it < 2; it++) {
        int s = tid + it * 256;
        int row = s >> 2, sg = s & 3;
        uint32_t off = (uint32_t)(row * 64 + ((sg ^ (row & 3)) * 16));
        cp16(aH + off, A + (size_t)(m0 + row) * EDIM + k0 + sg * 8);
    }
    {
        int row = tid >> 2, sg = tid & 3;
        uint32_t off = (uint32_t)(row * 64 + ((sg ^ (row & 3)) * 16));
        size_t gi = (size_t)(n0 + row) * EDIM + k0 + sg * 8;
        cp16(bH + off, Bh + gi);
        cp16(bL + off, Bl + gi);
    }
}

__device__ __forceinline__ void gemm_compute_stage(
    uint32_t sbase, int lane, int wm, int wn, float acc[2][4][4])
{
    uint32_t aH = sbase, bH = sbase + 8192, bL = sbase + 12288;
#pragma unroll
    for (int kc = 0; kc < 2; kc++) {
        uint32_t ah[2][4], bh[2][4], bl[2][4];
#pragma unroll
        for (int mt = 0; mt < 2; mt++) {
            int row = wm + mt * 16 + (lane & 15);
            int ch = (kc * 2 + (lane >> 4)) ^ (row & 3);
            ldmx4(ah[mt][0], ah[mt][1], ah[mt][2], ah[mt][3], aH + row * 64 + ch * 16);
        }
#pragma unroll
        for (int pr = 0; pr < 2; pr++) {
            int row = wn + pr * 16 + ((lane >> 4) << 3) + (lane & 7);
            int ch = (kc * 2 + ((lane >> 3) & 1)) ^ (row & 3);
            ldmx4(bh[pr][0], bh[pr][1], bh[pr][2], bh[pr][3], bH + row * 64 + ch * 16);
            ldmx4(bl[pr][0], bl[pr][1], bl[pr][2], bl[pr][3], bL + row * 64 + ch * 16);
        }
#pragma unroll
        for (int mt = 0; mt < 2; mt++)
#pragma unroll
            for (int nt = 0; nt < 4; nt++) {
                uint32_t b0h = bh[nt >> 1][(nt & 1) * 2], b1h = bh[nt >> 1][(nt & 1) * 2 + 1];
                uint32_t b0l = bl[nt >> 1][(nt & 1) * 2], b1l = bl[nt >> 1][(nt & 1) * 2 + 1];
                mma16816(acc[mt][nt], ah[mt], b0h, b1h);
                mma16816(acc[mt][nt], ah[mt], b0l, b1l);
            }
    }
}

// wait<1>; bar; compute(kt); issue load(kt+2); commit (always). S=3 ring.
#define GEMM_PIPE(Aptr, BHptr, BLptr)                                         \
    extern __shared__ __align__(16) char dynsm[];                             \
    const int tid = threadIdx.x, lane = tid & 31, warp = tid >> 5;            \
    const int wm = (warp >> 1) * 32, wn = (warp & 1) * 32;                    \
    const int m0 = blockIdx.x * 128, n0 = blockIdx.y * 64;                    \
    const uint32_t sb = smem_u32(dynsm);                                      \
    gemm_load_stage(sb,            Aptr, BHptr, BLptr, m0, n0, 0,  tid);      \
    cpcommit();                                                               \
    gemm_load_stage(sb + GSTG,     Aptr, BHptr, BLptr, m0, n0, 32, tid);      \
    cpcommit();                                                               \
    float acc[2][4][4] = {};                                                  \
    for (int kt = 0; kt < 24; kt++) {                                         \
        cpwait<1>();                                                          \
        __syncthreads();                                                      \
        gemm_compute_stage(sb + (kt % 3) * GSTG, lane, wm, wn, acc);          \
        if (kt + 2 < 24)                                                      \
            gemm_load_stage(sb + ((kt + 2) % 3) * GSTG, Aptr, BHptr, BLptr,   \
                            m0, n0, (kt + 2) * 32, tid);                      \
        cpcommit();                                                           \
    }

// ---------------------------------------------------------------------------
// Kernel 1: qkv projection. Grid (32, 36).
// ---------------------------------------------------------------------------
__global__ __launch_bounds__(256) void qkv_gemm_kernel(const float* __restrict__ bias)
{
    GEMM_PIPE(g_qxh, g_wih, g_wil)

    const int g = lane >> 2, c = lane & 3;
    const int sec = blockIdx.y / 12, hh = blockIdx.y % 12;
#pragma unroll
    for (int mt = 0; mt < 2; mt++)
#pragma unroll
        for (int nt = 0; nt < 4; nt++) {
            int dloc = wn + nt * 8 + 2 * c;
            float bv0 = bias[n0 + dloc], bv1 = bias[n0 + dloc + 1];
#pragma unroll
            for (int rr = 0; rr < 2; rr++) {
                int row = m0 + wm + mt * 16 + g + rr * 8;
                int node = row >> 2, bg = row & 3;
                float v0 = acc[mt][nt][rr * 2 + 0] + bv0;
                float v1 = acc[mt][nt][rr * 2 + 1] + bv1;
                size_t idx = (((size_t)(bg * NH + hh) * NNODE + node) * HD + dloc);
                if (sec == 0) {
                    *(uint32_t*)&g_qh[idx] = pack_half2(v0 * QSCALE, v1 * QSCALE);
                } else {
                    uint32_t ph, pl;
                    split2h(v0, v1, ph, pl);
                    if (sec == 1) { *(uint32_t*)&g_kh[idx] = ph; *(uint32_t*)&g_kl[idx] = pl; }
                    else          { *(uint32_t*)&g_vh[idx] = ph; *(uint32_t*)&g_vl[idx] = pl; }
                }
            }
        }
}

// ---------------------------------------------------------------------------
// Kernel 3: out projection + mask. Grid (32, 12).
// ---------------------------------------------------------------------------
__global__ __launch_bounds__(256) void out_gemm_kernel(
    const float* __restrict__ bias, const void* __restrict__ maskp,
    float* __restrict__ out)
{
    GEMM_PIPE(g_ah, g_woh, g_wol)

    const int g = lane >> 2, c = lane & 3;
    const int mkind = g_mask_kind;
#pragma unroll
    for (int mt = 0; mt < 2; mt++)
#pragma unroll
        for (int rr = 0; rr < 2; rr++) {
            int row = m0 + wm + mt * 16 + g + rr * 8;
            int node = row >> 2, bg = row & 3;
            int midx = bg * NNODE + node;
            bool keep;
            if (mkind == 1)      keep = ((const int*)maskp)[midx] != 0;
            else if (mkind == 2) keep = ((const float*)maskp)[midx] != 0.0f;
            else                 keep = ((const uint8_t*)maskp)[midx] != 0;
#pragma unroll
            for (int nt = 0; nt < 4; nt++) {
                int col = n0 + wn + nt * 8 + 2 * c;
                float v0 = keep ? (acc[mt][nt][rr * 2 + 0] + bias[col])     : 0.0f;
                float v1 = keep ? (acc[mt][nt][rr * 2 + 1] + bias[col + 1]) : 0.0f;
                *(float2*)&out[(size_t)row * EDIM + col] = make_float2(v0, v1);
            }
        }
}

// ============================================================================
// Kernel 2: flash attention. CTA = 128 q-rows x 1 head, 8 warps.
// 32 key-stages of 32 keys; 3-stage cp.async ring, one barrier per stage.
// Q rounded fp16; K,V split hi/lo; P rounded fp16 (no split).
// ============================================================================
#define ASTG 34816            // Kh 4096 Kl 4096 Vh 4096 Vl 4096 bias 128*36*4
#define BIAS_PITCH 36

__device__ __forceinline__ void attn_load_stage(
    uint32_t sbase, size_t kvbase, const float* bb, int m0, int n0, int tid)
{
    uint32_t kH = sbase, kL = sbase + 4096, vH = sbase + 8192, vL = sbase + 12288;
    uint32_t bS = sbase + 16384;
    {
        int row = tid >> 3, ch = tid & 7;
        uint32_t off = (uint32_t)(row * 128 + ((ch ^ (row & 7)) * 16));
        size_t gi = kvbase + (size_t)(m0 + row) * HD + ch * 8;
        cp16(kH + off, g_kh + gi);
        cp16(kL + off, g_kl + gi);
        cp16(vH + off, g_vh + gi);
        cp16(vL + off, g_vl + gi);
    }
#pragma unroll
    for (int it = 0; it < 4; it++) {
        int s = tid + it * 256;
        int row = s >> 3, ch = s & 7;
        cp16(bS + (uint32_t)(row * (BIAS_PITCH * 4) + ch * 16),
             bb + (size_t)(n0 + row) * NNODE + m0 + ch * 4);
    }
}

__global__ __launch_bounds__(256) void attn_kernel(const float* __restrict__ bias)
{
    extern __shared__ __align__(16) char dynsm[];
    const int tid = threadIdx.x, lane = tid & 31, warp = tid >> 5;
    const int bh = blockIdx.y, n0 = blockIdx.x * 128;
    const size_t base = (size_t)bh * NNODE * HD;
    const float* bb = bias + ((size_t)bh << 20);

    const uint32_t qH = smem_u32(dynsm);
    const uint32_t st0 = qH + 16384;

    // prologue: group0 = Q + stage0; group1 = stage1
#pragma unroll
    for (int it = 0; it < 4; it++) {
        int s = tid + it * 256;
        int row = s >> 3, ch = s & 7;
        uint32_t off = (uint32_t)(row * 128 + ((ch ^ (row & 7)) * 16));
        cp16(qH + off, g_qh + base + (size_t)(n0 + row) * HD + ch * 8);
    }
    attn_load_stage(st0, base, bb, 0, n0, tid);
    cpcommit();
    attn_load_stage(st0 + ASTG, base, bb, 32, n0, tid);
    cpcommit();

    uint32_t qh[4][4];
    float o[8][4] = {};
    float mrow0 = -1e30f, mrow1 = -1e30f, lrow0 = 0.f, lrow1 = 0.f;
    const int g = lane >> 2, c = lane & 3;

    for (int t = 0; t < 32; t++) {
        cpwait<1>();
        __syncthreads();
        if (t == 0) {
#pragma unroll
            for (int kc = 0; kc < 4; kc++) {
                int row = warp * 16 + (lane & 15);
                int ch = (kc * 2 + (lane >> 4)) ^ (row & 7);
                ldmx4(qh[kc][0], qh[kc][1], qh[kc][2], qh[kc][3], qH + row * 128 + ch * 16);
            }
        }

        const uint32_t cur = st0 + (t % 3) * ASTG;
        const uint32_t kH = cur, kL = cur + 4096, vH = cur + 8192, vL = cur + 12288;
        const float* bsm = (const float*)(dynsm + (cur - qH) + 16384);

        // S = Qh Kh^T + Qh Kl^T
        float sfr[4][4] = {};
#pragma unroll
        for (int kc = 0; kc < 4; kc++) {
            uint32_t kbh[2][4], kbl[2][4];
#pragma unroll
            for (int pr = 0; pr < 2; pr++) {
                int row = pr * 16 + ((lane >> 4) << 3) + (lane & 7);
                int ch = (kc * 2 + ((lane >> 3) & 1)) ^ (row & 7);
                ldmx4(kbh[pr][0], kbh[pr][1], kbh[pr][2], kbh[pr][3], kH + row * 128 + ch * 16);
                ldmx4(kbl[pr][0], kbl[pr][1], kbl[pr][2], kbl[pr][3], kL + row * 128 + ch * 16);
            }
#pragma unroll
            for (int nt = 0; nt < 4; nt++) {
                uint32_t b0h = kbh[nt >> 1][(nt & 1) * 2], b1h = kbh[nt >> 1][(nt & 1) * 2 + 1];
                uint32_t b0l = kbl[nt >> 1][(nt & 1) * 2], b1l = kbl[nt >> 1][(nt & 1) * 2 + 1];
                mma16816(sfr[nt], qh[kc], b0h, b1h);
                mma16816(sfr[nt], qh[kc], b0l, b1l);
            }
        }

        // bias (smem) + online softmax for rows g and g+8
        float mx0 = -1e30f, mx1 = -1e30f;
#pragma unroll
        for (int nt = 0; nt < 4; nt++) {
            int col = nt * 8 + 2 * c;
            float2 b01 = *(const float2*)(bsm + (warp * 16 + g) * BIAS_PITCH + col);
            float2 b23 = *(const float2*)(bsm + (warp * 16 + g + 8) * BIAS_PITCH + col);
            sfr[nt][0] += b01.x; sfr[nt][1] += b01.y;
            sfr[nt][2] += b23.x; sfr[nt][3] += b23.y;
            mx0 = fmaxf(mx0, fmaxf(sfr[nt][0], sfr[nt][1]));
            mx1 = fmaxf(mx1, fmaxf(sfr[nt][2], sfr[nt][3]));
        }
        mx0 = fmaxf(mx0, __shfl_xor_sync(0xffffffffu, mx0, 1));
        mx0 = fmaxf(mx0, __shfl_xor_sync(0xffffffffu, mx0, 2));
        mx1 = fmaxf(mx1, __shfl_xor_sync(0xffffffffu, mx1, 1));
        mx1 = fmaxf(mx1, __shfl_xor_sync(0xffffffffu, mx1, 2));
        float mn0 = fmaxf(mrow0, mx0), mn1 = fmaxf(mrow1, mx1);
        float al0 = __expf(mrow0 - mn0), al1 = __expf(mrow1 - mn1);
        mrow0 = mn0; mrow1 = mn1;
        float sum0 = 0.f, sum1 = 0.f;
#pragma unroll
        for (int nt = 0; nt < 4; nt++) {
            sfr[nt][0] = __expf(sfr[nt][0] - mn0);
            sfr[nt][1] = __expf(sfr[nt][1] - mn0);
            sfr[nt][2] = __expf(sfr[nt][2] - mn1);
            sfr[nt][3] = __expf(sfr[nt][3] - mn1);
            sum0 += sfr[nt][0] + sfr[nt][1];
            sum1 += sfr[nt][2] + sfr[nt][3];
        }
        sum0 += __shfl_xor_sync(0xffffffffu, sum0, 1);
        sum0 += __shfl_xor_sync(0xffffffffu, sum0, 2);
        sum1 += __shfl_xor_sync(0xffffffffu, sum1, 1);
        sum1 += __shfl_xor_sync(0xffffffffu, sum1, 2);
        lrow0 = lrow0 * al0 + sum0;
        lrow1 = lrow1 * al1 + sum1;
#pragma unroll
        for (int nt = 0; nt < 8; nt++) {
            o[nt][0] *= al0; o[nt][1] *= al0;
            o[nt][2] *= al1; o[nt][3] *= al1;
        }

        // O += Ph (Vh + Vl), P rounded to fp16 in registers
#pragma unroll
        for (int kc = 0; kc < 2; kc++) {
            uint32_t pa[4];
            pa[0] = pack_half2(sfr[2 * kc][0],     sfr[2 * kc][1]);
            pa[1] = pack_half2(sfr[2 * kc][2],     sfr[2 * kc][3]);
            pa[2] = pack_half2(sfr[2 * kc + 1][0], sfr[2 * kc + 1][1]);
            pa[3] = pack_half2(sfr[2 * kc + 1][2], sfr[2 * kc + 1][3]);
#pragma unroll
            for (int pr = 0; pr < 4; pr++) {
                int row = kc * 16 + ((lane >> 3) & 1) * 8 + (lane & 7);
                int ch = (2 * pr + (lane >> 4)) ^ (row & 7);
                uint32_t vh0, vh1, vh2, vh3, vl0, vl1, vl2, vl3;
                ldmx4t(vh0, vh1, vh2, vh3, vH + row * 128 + ch * 16);
                ldmx4t(vl0, vl1, vl2, vl3, vL + row * 128 + ch * 16);
                mma16816(o[2 * pr],     pa, vh0, vh1);
                mma16816(o[2 * pr],     pa, vl0, vl1);
                mma16816(o[2 * pr + 1], pa, vh2, vh3);
                mma16816(o[2 * pr + 1], pa, vl2, vl3);
            }
        }

        if (t + 2 < 32)
            attn_load_stage(st0 + ((t + 2) % 3) * ASTG, base, bb, (t + 2) * 32, n0, tid);
        cpcommit();
    }

    // epilogue: normalize, round to fp16, store [N, B, E]
    const float inv0 = 1.f / lrow0, inv1 = 1.f / lrow1;
    const int bg = bh / NH, hh = bh - bg * NH;
    const int r0g = n0 + warp * 16 + g;
#pragma unroll
    for (int nt = 0; nt < 8; nt++) {
        int d = nt * 8 + 2 * c;
        size_t i0 = ((size_t)r0g * NG + bg) * EDIM + hh * HD + d;
        size_t i1 = ((size_t)(r0g + 8) * NG + bg) * EDIM + hh * HD + d;
        *(uint32_t*)&g_ah[i0] = pack_half2(o[nt][0] * inv0, o[nt][1] * inv0);
        *(uint32_t*)&g_ah[i1] = pack_half2(o[nt][2] * inv1, o[nt][3] * inv1);
    }
}

// ---------------------------------------------------------------------------
extern "C" void kernel_launch(void* const* d_in, const int* in_sizes, int n_in,
                              void* d_out, int out_size) {
    const float* query     = (const float*)d_in[0];
    const float* attn_bias = (const float*)d_in[1];
    const void*  mask      = d_in[2];
    const float* W_in      = (const float*)d_in[3];
    const float* b_in      = (const float*)d_in[4];
    const float* W_out     = (const float*)d_in[5];
    const float* b_out     = (const float*)d_in[6];
    float* out = (float*)d_out;

    detect_mask_kernel<<<1, 256>>>((const uint8_t*)mask);
    split_q_kernel<<<768,  256>>>((const float4*)query, MROWS * EDIM / 4);
    split_w_kernel<<<1184, 256>>>((const float4*)W_in,  1, 3 * EDIM * EDIM / 4);
    split_w_kernel<<<592,  256>>>((const float4*)W_out, 2, EDIM * EDIM / 4);

    const int gsm = 3 * GSTG;  // 48 KB
    cudaFuncSetAttribute((const void*)qkv_gemm_kernel,
                         cudaFuncAttributeMaxDynamicSharedMemorySize, gsm);
    cudaFuncSetAttribute((const void*)out_gemm_kernel,
                         cudaFuncAttributeMaxDynamicSharedMemorySize, gsm);
    qkv_gemm_kernel<<<dim3(32, 36), 256, gsm>>>(b_in);

    const int asmb = 16384 + 3 * ASTG;  // 120832
    cudaFuncSetAttribute((const void*)attn_kernel,
                         cudaFuncAttributeMaxDynamicSharedMemorySize, asmb);
    attn_kernel<<<dim3(8, BHD), 256, asmb>>>(attn_bias);

    out_gemm_kernel<<<dim3(32, 12), 256, gsm>>>(b_out, mask, out);
}

// round 5
// speedup vs baseline: 4.4760x; 1.1325x over previous
#include <cuda_runtime.h>
#include <cuda_fp16.h>
#include <cstdint>

#define NG    4
#define NH    12
#define BHD   48
#define NNODE 1024
#define EDIM  768
#define HD    64
#define QSCALE 0.125f
#define MROWS 4096

// ---------------- scratch (no cudaMalloc allowed) ----------------
__device__ __half g_qxh[MROWS * EDIM];                           // query rounded fp16
__device__ __half g_wih[3 * EDIM * EDIM], g_wil[3 * EDIM * EDIM];// W_in hi/lo
__device__ __half g_woh[EDIM * EDIM],     g_wol[EDIM * EDIM];    // W_out hi/lo
__device__ __half g_qh[BHD * NNODE * HD];                        // q rounded (scaled)
__device__ __half g_kh[BHD * NNODE * HD], g_kl[BHD * NNODE * HD];
__device__ __half g_vh[BHD * NNODE * HD], g_vl[BHD * NNODE * HD];
__device__ __half g_ah[MROWS * EDIM];                            // attn out rounded
__device__ int    g_mask_kind;

// ---------------- helpers ----------------
__device__ __forceinline__ uint32_t smem_u32(const void* p) {
    return (uint32_t)__cvta_generic_to_shared(p);
}
__device__ __forceinline__ void cp16(uint32_t dst, const void* src) {
    asm volatile("cp.async.cg.shared.global [%0],[%1],16;\n" :: "r"(dst), "l"(src) : "memory");
}
__device__ __forceinline__ void cpcommit() {
    asm volatile("cp.async.commit_group;\n" ::: "memory");
}
template<int N> __device__ __forceinline__ void cpwait() {
    asm volatile("cp.async.wait_group %0;\n" :: "n"(N) : "memory");
}
__device__ __forceinline__ void ldmx4(uint32_t& r0, uint32_t& r1, uint32_t& r2, uint32_t& r3, uint32_t a) {
    asm volatile("ldmatrix.sync.aligned.m8n8.x4.shared.b16 {%0,%1,%2,%3},[%4];\n"
                 : "=r"(r0), "=r"(r1), "=r"(r2), "=r"(r3) : "r"(a));
}
__device__ __forceinline__ void ldmx4t(uint32_t& r0, uint32_t& r1, uint32_t& r2, uint32_t& r3, uint32_t a) {
    asm volatile("ldmatrix.sync.aligned.m8n8.x4.trans.shared.b16 {%0,%1,%2,%3},[%4];\n"
                 : "=r"(r0), "=r"(r1), "=r"(r2), "=r"(r3) : "r"(a));
}
__device__ __forceinline__ void mma16816(float* c, const uint32_t* a, uint32_t b0, uint32_t b1) {
    asm volatile("mma.sync.aligned.m16n8k16.row.col.f32.f16.f16.f32 "
                 "{%0,%1,%2,%3},{%4,%5,%6,%7},{%8,%9},{%0,%1,%2,%3};\n"
                 : "+f"(c[0]), "+f"(c[1]), "+f"(c[2]), "+f"(c[3])
                 : "r"(a[0]), "r"(a[1]), "r"(a[2]), "r"(a[3]), "r"(b0), "r"(b1));
}
__device__ __forceinline__ uint32_t pack_half2(float x, float y) {
    __half2 h = __floats2half2_rn(x, y);
    return *reinterpret_cast<uint32_t*>(&h);
}
__device__ __forceinline__ void split2h(float v0, float v1, uint32_t& h, uint32_t& l) {
    __half b0 = __float2half_rn(v0), b1 = __float2half_rn(v1);
    float l0 = v0 - __half2float(b0);
    float l1 = v1 - __half2float(b1);
    uint16_t u0 = *reinterpret_cast<uint16_t*>(&b0);
    uint16_t u1 = *reinterpret_cast<uint16_t*>(&b1);
    h = (uint32_t)u0 | ((uint32_t)u1 << 16);
    l = pack_half2(l0, l1);
}

// ---------------- mask dtype probe ----------------
__global__ void detect_mask_kernel(const uint8_t* __restrict__ m) {
    __shared__ int or_b0, or_b123;
    if (threadIdx.x == 0) { or_b0 = 0; or_b123 = 0; }
    __syncthreads();
    int a0 = 0, a123 = 0;
    for (int w = threadIdx.x; w < 1024; w += blockDim.x) {
        a0   |= m[4 * w];
        a123 |= m[4 * w + 1] | m[4 * w + 2] | m[4 * w + 3];
    }
    if (a0)   atomicOr(&or_b0, 1);
    if (a123) atomicOr(&or_b123, 1);
    __syncthreads();
    if (threadIdx.x == 0) {
        if (or_b0 == 0)        g_mask_kind = 2;
        else if (or_b123 == 0) g_mask_kind = 1;
        else                   g_mask_kind = 0;
    }
}

// ---------------- fused prep: query rounded; W_in, W_out split ----------------
#define NQ4  (MROWS * EDIM / 4)          // 196608
#define NWI4 (3 * EDIM * EDIM / 4)       // 442368
#define NWO4 (EDIM * EDIM / 4)           // 147456
__global__ void prep_kernel(const float4* __restrict__ q,
                            const float4* __restrict__ wi,
                            const float4* __restrict__ wo) {
    int i = blockIdx.x * blockDim.x + threadIdx.x;
    if (i < NQ4) {
        float4 f = q[i];
        ((uint2*)g_qxh)[i] = make_uint2(pack_half2(f.x, f.y), pack_half2(f.z, f.w));
    } else if (i < NQ4 + NWI4) {
        int j = i - NQ4;
        float4 f = wi[j];
        uint32_t h0, l0, h1, l1;
        split2h(f.x, f.y, h0, l0);
        split2h(f.z, f.w, h1, l1);
        ((uint2*)g_wih)[j] = make_uint2(h0, h1);
        ((uint2*)g_wil)[j] = make_uint2(l0, l1);
    } else if (i < NQ4 + NWI4 + NWO4) {
        int j = i - NQ4 - NWI4;
        float4 f = wo[j];
        uint32_t h0, l0, h1, l1;
        split2h(f.x, f.y, h0, l0);
        split2h(f.z, f.w, h1, l1);
        ((uint2*)g_woh)[j] = make_uint2(h0, h1);
        ((uint2*)g_wol)[j] = make_uint2(l0, l1);
    }
}

// ============================================================================
// GEMM core: BM=128, BN=128, BK=32, 256 threads (8 warps 2x4), warp 64x32.
// A rounded fp16, B split hi/lo. 3-stage cp.async, one barrier per k-iter.
// ============================================================================
#define GSTG 24576   // A 8192 + Bh 8192 + Bl 8192

__device__ __forceinline__ void gemm_load_stage(
    uint32_t sbase, const __half* A, const __half* Bh, const __half* Bl,
    int m0, int n0, int k0, int tid)
{
    uint32_t aH = sbase, bH = sbase + 8192, bL = sbase + 16384;
#pragma unroll
    for (int it = 0; it < 2; it++) {
        int s = tid + it * 256;
        int row = s >> 2, sg = s & 3;
        uint32_t off = (uint32_t)(row * 64 + ((sg ^ (row & 3)) * 16));
        cp16(aH + off, A + (size_t)(m0 + row) * EDIM + k0 + sg * 8);
        size_t gi = (size_t)(n0 + row) * EDIM + k0 + sg * 8;
        cp16(bH + off, Bh + gi);
        cp16(bL + off, Bl + gi);
    }
}

__device__ __forceinline__ void gemm_compute_stage(
    uint32_t sbase, int lane, int wm, int wn, float acc[4][4][4])
{
    uint32_t aH = sbase, bH = sbase + 8192, bL = sbase + 16384;
#pragma unroll
    for (int kc = 0; kc < 2; kc++) {
        uint32_t ah[4][4], bh[2][4], bl[2][4];
#pragma unroll
        for (int mt = 0; mt < 4; mt++) {
            int row = wm + mt * 16 + (lane & 15);
            int ch = (kc * 2 + (lane >> 4)) ^ (row & 3);
            ldmx4(ah[mt][0], ah[mt][1], ah[mt][2], ah[mt][3], aH + row * 64 + ch * 16);
        }
#pragma unroll
        for (int pr = 0; pr < 2; pr++) {
            int row = wn + pr * 16 + ((lane >> 4) << 3) + (lane & 7);
            int ch = (kc * 2 + ((lane >> 3) & 1)) ^ (row & 3);
            ldmx4(bh[pr][0], bh[pr][1], bh[pr][2], bh[pr][3], bH + row * 64 + ch * 16);
            ldmx4(bl[pr][0], bl[pr][1], bl[pr][2], bl[pr][3], bL + row * 64 + ch * 16);
        }
#pragma unroll
        for (int mt = 0; mt < 4; mt++)
#pragma unroll
            for (int nt = 0; nt < 4; nt++) {
                uint32_t b0h = bh[nt >> 1][(nt & 1) * 2], b1h = bh[nt >> 1][(nt & 1) * 2 + 1];
                uint32_t b0l = bl[nt >> 1][(nt & 1) * 2], b1l = bl[nt >> 1][(nt & 1) * 2 + 1];
                mma16816(acc[mt][nt], ah[mt], b0h, b1h);
                mma16816(acc[mt][nt], ah[mt], b0l, b1l);
            }
    }
}

#define GEMM_PIPE(Aptr, BHptr, BLptr)                                         \
    extern __shared__ __align__(16) char dynsm[];                             \
    const int tid = threadIdx.x, lane = tid & 31, warp = tid >> 5;            \
    const int wm = (warp >> 2) * 64, wn = (warp & 3) * 32;                    \
    const int m0 = blockIdx.x * 128, n0 = blockIdx.y * 128;                   \
    const uint32_t sb = smem_u32(dynsm);                                      \
    gemm_load_stage(sb,        Aptr, BHptr, BLptr, m0, n0, 0,  tid);          \
    cpcommit();                                                               \
    gemm_load_stage(sb + GSTG, Aptr, BHptr, BLptr, m0, n0, 32, tid);          \
    cpcommit();                                                               \
    float acc[4][4][4] = {};                                                  \
    for (int kt = 0; kt < 24; kt++) {                                         \
        cpwait<1>();                                                          \
        __syncthreads();                                                      \
        gemm_compute_stage(sb + (kt % 3) * GSTG, lane, wm, wn, acc);          \
        if (kt + 2 < 24)                                                      \
            gemm_load_stage(sb + ((kt + 2) % 3) * GSTG, Aptr, BHptr, BLptr,   \
                            m0, n0, (kt + 2) * 32, tid);                      \
        cpcommit();                                                           \
    }

// ---------------------------------------------------------------------------
// Kernel 1: qkv projection. Grid (32, 18).
// ---------------------------------------------------------------------------
__global__ __launch_bounds__(256) void qkv_gemm_kernel(const float* __restrict__ bias)
{
    GEMM_PIPE(g_qxh, g_wih, g_wil)

    const int g = lane >> 2, c = lane & 3;
    const int sec = n0 / EDIM;
    const int colbase = n0 - sec * EDIM;       // 128-aligned within section
#pragma unroll
    for (int mt = 0; mt < 4; mt++)
#pragma unroll
        for (int nt = 0; nt < 4; nt++) {
            int dloc = wn + nt * 8 + 2 * c;    // 0..127 within block n-tile
            int e = colbase + dloc;
            int hh = e >> 6, d = e & 63;
            float bv0 = bias[n0 + dloc], bv1 = bias[n0 + dloc + 1];
#pragma unroll
            for (int rr = 0; rr < 2; rr++) {
                int row = m0 + wm + mt * 16 + g + rr * 8;
                int node = row >> 2, bg = row & 3;
                float v0 = acc[mt][nt][rr * 2 + 0] + bv0;
                float v1 = acc[mt][nt][rr * 2 + 1] + bv1;
                size_t idx = (((size_t)(bg * NH + hh) * NNODE + node) * HD + d);
                if (sec == 0) {
                    *(uint32_t*)&g_qh[idx] = pack_half2(v0 * QSCALE, v1 * QSCALE);
                } else {
                    uint32_t ph, pl;
                    split2h(v0, v1, ph, pl);
                    if (sec == 1) { *(uint32_t*)&g_kh[idx] = ph; *(uint32_t*)&g_kl[idx] = pl; }
                    else          { *(uint32_t*)&g_vh[idx] = ph; *(uint32_t*)&g_vl[idx] = pl; }
                }
            }
        }
}

// ---------------------------------------------------------------------------
// Kernel 3: out projection + mask. Grid (32, 6).
// ---------------------------------------------------------------------------
__global__ __launch_bounds__(256) void out_gemm_kernel(
    const float* __restrict__ bias, const void* __restrict__ maskp,
    float* __restrict__ out)
{
    GEMM_PIPE(g_ah, g_woh, g_wol)

    const int g = lane >> 2, c = lane & 3;
    const int mkind = g_mask_kind;
#pragma unroll
    for (int mt = 0; mt < 4; mt++)
#pragma unroll
        for (int rr = 0; rr < 2; rr++) {
            int row = m0 + wm + mt * 16 + g + rr * 8;
            int node = row >> 2, bg = row & 3;
            int midx = bg * NNODE + node;
            bool keep;
            if (mkind == 1)      keep = ((const int*)maskp)[midx] != 0;
            else if (mkind == 2) keep = ((const float*)maskp)[midx] != 0.0f;
            else                 keep = ((const uint8_t*)maskp)[midx] != 0;
#pragma unroll
            for (int nt = 0; nt < 4; nt++) {
                int col = n0 + wn + nt * 8 + 2 * c;
                float v0 = keep ? (acc[mt][nt][rr * 2 + 0] + bias[col])     : 0.0f;
                float v1 = keep ? (acc[mt][nt][rr * 2 + 1] + bias[col + 1]) : 0.0f;
                *(float2*)&out[(size_t)row * EDIM + col] = make_float2(v0, v1);
            }
        }
}

// ============================================================================
// Kernel 2: flash attention. CTA = 128 q-rows x 1 head, 8 warps.
// 16 key-stages of 64 keys; 3-stage cp.async ring, one barrier per stage.
// Q rounded fp16; K,V split hi/lo; P rounded fp16 (no split).
// ============================================================================
#define BIAS_PITCH 68
#define ASTG (32768 + 128 * BIAS_PITCH * 4)   // Kh/Kl/Vh/Vl 8192 each + bias 34816

__device__ __forceinline__ void attn_load_stage(
    uint32_t sbase, size_t kvbase, const float* bb, int m0, int n0, int tid)
{
    uint32_t kH = sbase, kL = sbase + 8192, vH = sbase + 16384, vL = sbase + 24576;
    uint32_t bS = sbase + 32768;
#pragma unroll
    for (int it = 0; it < 2; it++) {
        int s = tid + it * 256;
        int row = s >> 3, ch = s & 7;
        uint32_t off = (uint32_t)(row * 128 + ((ch ^ (row & 7)) * 16));
        size_t gi = kvbase + (size_t)(m0 + row) * HD + ch * 8;
        cp16(kH + off, g_kh + gi);
        cp16(kL + off, g_kl + gi);
        cp16(vH + off, g_vh + gi);
        cp16(vL + off, g_vl + gi);
    }
#pragma unroll
    for (int it = 0; it < 8; it++) {
        int s = tid + it * 256;
        int row = s >> 4, ch = s & 15;
        cp16(bS + (uint32_t)(row * (BIAS_PITCH * 4) + ch * 16),
             bb + (size_t)(n0 + row) * NNODE + m0 + ch * 4);
    }
}

__global__ __launch_bounds__(256) void attn_kernel(const float* __restrict__ bias)
{
    extern __shared__ __align__(16) char dynsm[];
    const int tid = threadIdx.x, lane = tid & 31, warp = tid >> 5;
    const int bh = blockIdx.y, n0 = blockIdx.x * 128;
    const size_t base = (size_t)bh * NNODE * HD;
    const float* bb = bias + ((size_t)bh << 20);

    const uint32_t qH = smem_u32(dynsm);
    const uint32_t st0 = qH + 16384;

    // prologue
#pragma unroll
    for (int it = 0; it < 4; it++) {
        int s = tid + it * 256;
        int row = s >> 3, ch = s & 7;
        uint32_t off = (uint32_t)(row * 128 + ((ch ^ (row & 7)) * 16));
        cp16(qH + off, g_qh + base + (size_t)(n0 + row) * HD + ch * 8);
    }
    attn_load_stage(st0, base, bb, 0, n0, tid);
    cpcommit();
    attn_load_stage(st0 + ASTG, base, bb, 64, n0, tid);
    cpcommit();

    uint32_t qh[4][4];
    float o[8][4] = {};
    float mrow0 = -1e30f, mrow1 = -1e30f, lrow0 = 0.f, lrow1 = 0.f;
    const int g = lane >> 2, c = lane & 3;

    for (int t = 0; t < 16; t++) {
        cpwait<1>();
        __syncthreads();
        if (t == 0) {
#pragma unroll
            for (int kc = 0; kc < 4; kc++) {
                int row = warp * 16 + (lane & 15);
                int ch = (kc * 2 + (lane >> 4)) ^ (row & 7);
                ldmx4(qh[kc][0], qh[kc][1], qh[kc][2], qh[kc][3], qH + row * 128 + ch * 16);
            }
        }

        const uint32_t cur = st0 + (t % 3) * ASTG;
        const uint32_t kH = cur, kL = cur + 8192, vH = cur + 16384, vL = cur + 24576;
        const float* bsm = (const float*)(dynsm + (cur - qH) + 32768);

        // S = Qh Kh^T + Qh Kl^T over 64 keys
        float sfr[8][4] = {};
#pragma unroll
        for (int kc = 0; kc < 4; kc++) {
            uint32_t kbh[4][4], kbl[4][4];
#pragma unroll
            for (int pr = 0; pr < 4; pr++) {
                int row = pr * 16 + ((lane >> 4) << 3) + (lane & 7);
                int ch = (kc * 2 + ((lane >> 3) & 1)) ^ (row & 7);
                ldmx4(kbh[pr][0], kbh[pr][1], kbh[pr][2], kbh[pr][3], kH + row * 128 + ch * 16);
                ldmx4(kbl[pr][0], kbl[pr][1], kbl[pr][2], kbl[pr][3], kL + row * 128 + ch * 16);
            }
#pragma unroll
            for (int nt = 0; nt < 8; nt++) {
                uint32_t b0h = kbh[nt >> 1][(nt & 1) * 2], b1h = kbh[nt >> 1][(nt & 1) * 2 + 1];
                uint32_t b0l = kbl[nt >> 1][(nt & 1) * 2], b1l = kbl[nt >> 1][(nt & 1) * 2 + 1];
                mma16816(sfr[nt], qh[kc], b0h, b1h);
                mma16816(sfr[nt], qh[kc], b0l, b1l);
            }
        }

        // bias (smem) + online softmax for rows g and g+8
        float mx0 = -1e30f, mx1 = -1e30f;
#pragma unroll
        for (int nt = 0; nt < 8; nt++) {
            int col = nt * 8 + 2 * c;
            float2 b01 = *(const float2*)(bsm + (warp * 16 + g) * BIAS_PITCH + col);
            float2 b23 = *(const float2*)(bsm + (warp * 16 + g + 8) * BIAS_PITCH + col);
            sfr[nt][0] += b01.x; sfr[nt][1] += b01.y;
            sfr[nt][2] += b23.x; sfr[nt][3] += b23.y;
            mx0 = fmaxf(mx0, fmaxf(sfr[nt][0], sfr[nt][1]));
            mx1 = fmaxf(mx1, fmaxf(sfr[nt][2], sfr[nt][3]));
        }
        mx0 = fmaxf(mx0, __shfl_xor_sync(0xffffffffu, mx0, 1));
        mx0 = fmaxf(mx0, __shfl_xor_sync(0xffffffffu, mx0, 2));
        mx1 = fmaxf(mx1, __shfl_xor_sync(0xffffffffu, mx1, 1));
        mx1 = fmaxf(mx1, __shfl_xor_sync(0xffffffffu, mx1, 2));
        float mn0 = fmaxf(mrow0, mx0), mn1 = fmaxf(mrow1, mx1);
        float al0 = __expf(mrow0 - mn0), al1 = __expf(mrow1 - mn1);
        mrow0 = mn0; mrow1 = mn1;
        float sum0 = 0.f, sum1 = 0.f;
#pragma unroll
        for (int nt = 0; nt < 8; nt++) {
            sfr[nt][0] = __expf(sfr[nt][0] - mn0);
            sfr[nt][1] = __expf(sfr[nt][1] - mn0);
            sfr[nt][2] = __expf(sfr[nt][2] - mn1);
            sfr[nt][3] = __expf(sfr[nt][3] - mn1);
            sum0 += sfr[nt][0] + sfr[nt][1];
            sum1 += sfr[nt][2] + sfr[nt][3];
        }
        sum0 += __shfl_xor_sync(0xffffffffu, sum0, 1);
        sum0 += __shfl_xor_sync(0xffffffffu, sum0, 2);
        sum1 += __shfl_xor_sync(0xffffffffu, sum1, 1);
        sum1 += __shfl_xor_sync(0xffffffffu, sum1, 2);
        lrow0 = lrow0 * al0 + sum0;
        lrow1 = lrow1 * al1 + sum1;
#pragma unroll
        for (int nt = 0; nt < 8; nt++) {
            o[nt][0] *= al0; o[nt][1] *= al0;
            o[nt][2] *= al1; o[nt][3] *= al1;
        }

        // O += Ph (Vh + Vl); P rounded to fp16 in registers
#pragma unroll
        for (int kc = 0; kc < 4; kc++) {
            uint32_t pa[4];
            pa[0] = pack_half2(sfr[2 * kc][0],     sfr[2 * kc][1]);
            pa[1] = pack_half2(sfr[2 * kc][2],     sfr[2 * kc][3]);
            pa[2] = pack_half2(sfr[2 * kc + 1][0], sfr[2 * kc + 1][1]);
            pa[3] = pack_half2(sfr[2 * kc + 1][2], sfr[2 * kc + 1][3]);
#pragma unroll
            for (int pr = 0; pr < 4; pr++) {
                int row = kc * 16 + ((lane >> 3) & 1) * 8 + (lane & 7);
                int ch = (2 * pr + (lane >> 4)) ^ (row & 7);
                uint32_t vh0, vh1, vh2, vh3, vl0, vl1, vl2, vl3;
                ldmx4t(vh0, vh1, vh2, vh3, vH + row * 128 + ch * 16);
                ldmx4t(vl0, vl1, vl2, vl3, vL + row * 128 + ch * 16);
                mma16816(o[2 * pr],     pa, vh0, vh1);
                mma16816(o[2 * pr],     pa, vl0, vl1);
                mma16816(o[2 * pr + 1], pa, vh2, vh3);
                mma16816(o[2 * pr + 1], pa, vl2, vl3);
            }
        }

        if (t + 2 < 16)
            attn_load_stage(st0 + ((t + 2) % 3) * ASTG, base, bb, (t + 2) * 64, n0, tid);
        cpcommit();
    }

    // epilogue: normalize, round to fp16, store [N, B, E]
    const float inv0 = 1.f / lrow0, inv1 = 1.f / lrow1;
    const int bg = bh / NH, hh = bh - bg * NH;
    const int r0g = n0 + warp * 16 + g;
#pragma unroll
    for (int nt = 0; nt < 8; nt++) {
        int d = nt * 8 + 2 * c;
        size_t i0 = ((size_t)r0g * NG + bg) * EDIM + hh * HD + d;
        size_t i1 = ((size_t)(r0g + 8) * NG + bg) * EDIM + hh * HD + d;
        *(uint32_t*)&g_ah[i0] = pack_half2(o[nt][0] * inv0, o[nt][1] * inv0);
        *(uint32_t*)&g_ah[i1] = pack_half2(o[nt][2] * inv1, o[nt][3] * inv1);
    }
}

// ---------------------------------------------------------------------------
extern "C" void kernel_launch(void* const* d_in, const int* in_sizes, int n_in,
                              void* d_out, int out_size) {
    const float* query     = (const float*)d_in[0];
    const float* attn_bias = (const float*)d_in[1];
    const void*  mask      = d_in[2];
    const float* W_in      = (const float*)d_in[3];
    const float* b_in      = (const float*)d_in[4];
    const float* W_out     = (const float*)d_in[5];
    const float* b_out     = (const float*)d_in[6];
    float* out = (float*)d_out;

    detect_mask_kernel<<<1, 256>>>((const uint8_t*)mask);
    prep_kernel<<<(NQ4 + NWI4 + NWO4 + 255) / 256, 256>>>(
        (const float4*)query, (const float4*)W_in, (const float4*)W_out);

    const int gsm = 3 * GSTG;  // 72 KB
    cudaFuncSetAttribute((const void*)qkv_gemm_kernel,
                         cudaFuncAttributeMaxDynamicSharedMemorySize, gsm);
    cudaFuncSetAttribute((const void*)out_gemm_kernel,
                         cudaFuncAttributeMaxDynamicSharedMemorySize, gsm);
    qkv_gemm_kernel<<<dim3(32, 18), 256, gsm>>>(b_in);

    const int asmb = 16384 + 3 * ASTG;  // 219136
    cudaFuncSetAttribute((const void*)attn_kernel,
                         cudaFuncAttributeMaxDynamicSharedMemorySize, asmb);
    attn_kernel<<<dim3(8, BHD), 256, asmb>>>(attn_bias);

    out_gemm_kernel<<<dim3(32, 6), 256, gsm>>>(b_out, mask, out);
}

// round 6
// speedup vs baseline: 5.4319x; 1.2136x over previous
#include <cuda_runtime.h>
#include <cuda_fp16.h>
#include <cstdint>

#define NG    4
#define NH    12
#define BHD   48
#define NNODE 1024
#define EDIM  768
#define HD    64
#define QSCALE 0.125f
#define MROWS 4096

// ---------------- scratch (no cudaMalloc allowed) ----------------
__device__ __half g_qxh[MROWS * EDIM];                           // query rounded fp16
__device__ __half g_wih[3 * EDIM * EDIM], g_wil[3 * EDIM * EDIM];// W_in hi/lo
__device__ __half g_woh[EDIM * EDIM],     g_wol[EDIM * EDIM];    // W_out hi/lo
__device__ __half g_qh[BHD * NNODE * HD];                        // q rounded (scaled)
__device__ __half g_kh[BHD * NNODE * HD];                        // k rounded
__device__ __half g_vh[BHD * NNODE * HD];                        // v rounded
__device__ __half g_ah[MROWS * EDIM];                            // attn out rounded
__device__ int    g_mask_kind;

// ---------------- helpers ----------------
__device__ __forceinline__ uint32_t smem_u32(const void* p) {
    return (uint32_t)__cvta_generic_to_shared(p);
}
__device__ __forceinline__ void cp16(uint32_t dst, const void* src) {
    asm volatile("cp.async.cg.shared.global [%0],[%1],16;\n" :: "r"(dst), "l"(src) : "memory");
}
__device__ __forceinline__ void cpcommit() {
    asm volatile("cp.async.commit_group;\n" ::: "memory");
}
template<int N> __device__ __forceinline__ void cpwait() {
    asm volatile("cp.async.wait_group %0;\n" :: "n"(N) : "memory");
}
__device__ __forceinline__ void ldmx4(uint32_t& r0, uint32_t& r1, uint32_t& r2, uint32_t& r3, uint32_t a) {
    asm volatile("ldmatrix.sync.aligned.m8n8.x4.shared.b16 {%0,%1,%2,%3},[%4];\n"
                 : "=r"(r0), "=r"(r1), "=r"(r2), "=r"(r3) : "r"(a));
}
__device__ __forceinline__ void ldmx4t(uint32_t& r0, uint32_t& r1, uint32_t& r2, uint32_t& r3, uint32_t a) {
    asm volatile("ldmatrix.sync.aligned.m8n8.x4.trans.shared.b16 {%0,%1,%2,%3},[%4];\n"
                 : "=r"(r0), "=r"(r1), "=r"(r2), "=r"(r3) : "r"(a));
}
__device__ __forceinline__ void mma16816(float* c, const uint32_t* a, uint32_t b0, uint32_t b1) {
    asm volatile("mma.sync.aligned.m16n8k16.row.col.f32.f16.f16.f32 "
                 "{%0,%1,%2,%3},{%4,%5,%6,%7},{%8,%9},{%0,%1,%2,%3};\n"
                 : "+f"(c[0]), "+f"(c[1]), "+f"(c[2]), "+f"(c[3])
                 : "r"(a[0]), "r"(a[1]), "r"(a[2]), "r"(a[3]), "r"(b0), "r"(b1));
}
__device__ __forceinline__ uint32_t pack_half2(float x, float y) {
    __half2 h = __floats2half2_rn(x, y);
    return *reinterpret_cast<uint32_t*>(&h);
}
__device__ __forceinline__ void split2h(float v0, float v1, uint32_t& h, uint32_t& l) {
    __half b0 = __float2half_rn(v0), b1 = __float2half_rn(v1);
    float l0 = v0 - __half2float(b0);
    float l1 = v1 - __half2float(b1);
    uint16_t u0 = *reinterpret_cast<uint16_t*>(&b0);
    uint16_t u1 = *reinterpret_cast<uint16_t*>(&b1);
    h = (uint32_t)u0 | ((uint32_t)u1 << 16);
    l = pack_half2(l0, l1);
}

// ---------------- mask dtype probe ----------------
__global__ void detect_mask_kernel(const uint8_t* __restrict__ m) {
    __shared__ int or_b0, or_b123;
    if (threadIdx.x == 0) { or_b0 = 0; or_b123 = 0; }
    __syncthreads();
    int a0 = 0, a123 = 0;
    for (int w = threadIdx.x; w < 1024; w += blockDim.x) {
        a0   |= m[4 * w];
        a123 |= m[4 * w + 1] | m[4 * w + 2] | m[4 * w + 3];
    }
    if (a0)   atomicOr(&or_b0, 1);
    if (a123) atomicOr(&or_b123, 1);
    __syncthreads();
    if (threadIdx.x == 0) {
        if (or_b0 == 0)        g_mask_kind = 2;
        else if (or_b123 == 0) g_mask_kind = 1;
        else                   g_mask_kind = 0;
    }
}

// ---------------- fused prep: query rounded; W_in, W_out split ----------------
#define NQ4  (MROWS * EDIM / 4)          // 196608
#define NWI4 (3 * EDIM * EDIM / 4)       // 442368
#define NWO4 (EDIM * EDIM / 4)           // 147456
__global__ void prep_kernel(const float4* __restrict__ q,
                            const float4* __restrict__ wi,
                            const float4* __restrict__ wo) {
    int i = blockIdx.x * blockDim.x + threadIdx.x;
    if (i < NQ4) {
        float4 f = q[i];
        ((uint2*)g_qxh)[i] = make_uint2(pack_half2(f.x, f.y), pack_half2(f.z, f.w));
    } else if (i < NQ4 + NWI4) {
        int j = i - NQ4;
        float4 f = wi[j];
        uint32_t h0, l0, h1, l1;
        split2h(f.x, f.y, h0, l0);
        split2h(f.z, f.w, h1, l1);
        ((uint2*)g_wih)[j] = make_uint2(h0, h1);
        ((uint2*)g_wil)[j] = make_uint2(l0, l1);
    } else if (i < NQ4 + NWI4 + NWO4) {
        int j = i - NQ4 - NWI4;
        float4 f = wo[j];
        uint32_t h0, l0, h1, l1;
        split2h(f.x, f.y, h0, l0);
        split2h(f.z, f.w, h1, l1);
        ((uint2*)g_woh)[j] = make_uint2(h0, h1);
        ((uint2*)g_wol)[j] = make_uint2(l0, l1);
    }
}

// ============================================================================
// GEMM core: BM=128, BN=128, BK=32, 256 threads (8 warps 2x4), warp 64x32.
// A rounded fp16, B split hi/lo. 3-stage cp.async, one barrier per k-iter.
// ============================================================================
#define GSTG 24576   // A 8192 + Bh 8192 + Bl 8192

__device__ __forceinline__ void gemm_load_stage(
    uint32_t sbase, const __half* A, const __half* Bh, const __half* Bl,
    int m0, int n0, int k0, int tid)
{
    uint32_t aH = sbase, bH = sbase + 8192, bL = sbase + 16384;
#pragma unroll
    for (int it = 0; it < 2; it++) {
        int s = tid + it * 256;
        int row = s >> 2, sg = s & 3;
        uint32_t off = (uint32_t)(row * 64 + ((sg ^ (row & 3)) * 16));
        cp16(aH + off, A + (size_t)(m0 + row) * EDIM + k0 + sg * 8);
        size_t gi = (size_t)(n0 + row) * EDIM + k0 + sg * 8;
        cp16(bH + off, Bh + gi);
        cp16(bL + off, Bl + gi);
    }
}

__device__ __forceinline__ void gemm_compute_stage(
    uint32_t sbase, int lane, int wm, int wn, float acc[4][4][4])
{
    uint32_t aH = sbase, bH = sbase + 8192, bL = sbase + 16384;
#pragma unroll
    for (int kc = 0; kc < 2; kc++) {
        uint32_t ah[4][4], bh[2][4], bl[2][4];
#pragma unroll
        for (int mt = 0; mt < 4; mt++) {
            int row = wm + mt * 16 + (lane & 15);
            int ch = (kc * 2 + (lane >> 4)) ^ (row & 3);
            ldmx4(ah[mt][0], ah[mt][1], ah[mt][2], ah[mt][3], aH + row * 64 + ch * 16);
        }
#pragma unroll
        for (int pr = 0; pr < 2; pr++) {
            int row = wn + pr * 16 + ((lane >> 4) << 3) + (lane & 7);
            int ch = (kc * 2 + ((lane >> 3) & 1)) ^ (row & 3);
            ldmx4(bh[pr][0], bh[pr][1], bh[pr][2], bh[pr][3], bH + row * 64 + ch * 16);
            ldmx4(bl[pr][0], bl[pr][1], bl[pr][2], bl[pr][3], bL + row * 64 + ch * 16);
        }
#pragma unroll
        for (int mt = 0; mt < 4; mt++)
#pragma unroll
            for (int nt = 0; nt < 4; nt++) {
                uint32_t b0h = bh[nt >> 1][(nt & 1) * 2], b1h = bh[nt >> 1][(nt & 1) * 2 + 1];
                uint32_t b0l = bl[nt >> 1][(nt & 1) * 2], b1l = bl[nt >> 1][(nt & 1) * 2 + 1];
                mma16816(acc[mt][nt], ah[mt], b0h, b1h);
                mma16816(acc[mt][nt], ah[mt], b0l, b1l);
            }
    }
}

#define GEMM_PIPE(Aptr, BHptr, BLptr)                                         \
    extern __shared__ __align__(16) char dynsm[];                             \
    const int tid = threadIdx.x, lane = tid & 31, warp = tid >> 5;            \
    const int wm = (warp >> 2) * 64, wn = (warp & 3) * 32;                    \
    const int m0 = blockIdx.x * 128, n0 = blockIdx.y * 128;                   \
    const uint32_t sb = smem_u32(dynsm);                                      \
    gemm_load_stage(sb,        Aptr, BHptr, BLptr, m0, n0, 0,  tid);          \
    cpcommit();                                                               \
    gemm_load_stage(sb + GSTG, Aptr, BHptr, BLptr, m0, n0, 32, tid);          \
    cpcommit();                                                               \
    float acc[4][4][4] = {};                                                  \
    for (int kt = 0; kt < 24; kt++) {                                         \
        cpwait<1>();                                                          \
        __syncthreads();                                                      \
        gemm_compute_stage(sb + (kt % 3) * GSTG, lane, wm, wn, acc);          \
        if (kt + 2 < 24)                                                      \
            gemm_load_stage(sb + ((kt + 2) % 3) * GSTG, Aptr, BHptr, BLptr,   \
                            m0, n0, (kt + 2) * 32, tid);                      \
        cpcommit();                                                           \
    }

// ---------------------------------------------------------------------------
// Kernel 1: qkv projection. Grid (32, 18).
// ---------------------------------------------------------------------------
__global__ __launch_bounds__(256, 2) void qkv_gemm_kernel(const float* __restrict__ bias)
{
    GEMM_PIPE(g_qxh, g_wih, g_wil)

    const int g = lane >> 2, c = lane & 3;
    const int sec = n0 / EDIM;
    const int colbase = n0 - sec * EDIM;
    const float sc = (sec == 0) ? QSCALE : 1.0f;
    __half* dst = (sec == 0) ? g_qh : (sec == 1 ? g_kh : g_vh);
#pragma unroll
    for (int mt = 0; mt < 4; mt++)
#pragma unroll
        for (int nt = 0; nt < 4; nt++) {
            int dloc = wn + nt * 8 + 2 * c;
            int e = colbase + dloc;
            int hh = e >> 6, d = e & 63;
            float bv0 = bias[n0 + dloc], bv1 = bias[n0 + dloc + 1];
#pragma unroll
            for (int rr = 0; rr < 2; rr++) {
                int row = m0 + wm + mt * 16 + g + rr * 8;
                int node = row >> 2, bg = row & 3;
                float v0 = (acc[mt][nt][rr * 2 + 0] + bv0) * sc;
                float v1 = (acc[mt][nt][rr * 2 + 1] + bv1) * sc;
                size_t idx = (((size_t)(bg * NH + hh) * NNODE + node) * HD + d);
                *(uint32_t*)&dst[idx] = pack_half2(v0, v1);
            }
        }
}

// ---------------------------------------------------------------------------
// Kernel 3: out projection + mask. Grid (32, 6).
// ---------------------------------------------------------------------------
__global__ __launch_bounds__(256, 2) void out_gemm_kernel(
    const float* __restrict__ bias, const void* __restrict__ maskp,
    float* __restrict__ out)
{
    GEMM_PIPE(g_ah, g_woh, g_wol)

    const int g = lane >> 2, c = lane & 3;
    const int mkind = g_mask_kind;
#pragma unroll
    for (int mt = 0; mt < 4; mt++)
#pragma unroll
        for (int rr = 0; rr < 2; rr++) {
            int row = m0 + wm + mt * 16 + g + rr * 8;
            int node = row >> 2, bg = row & 3;
            int midx = bg * NNODE + node;
            bool keep;
            if (mkind == 1)      keep = ((const int*)maskp)[midx] != 0;
            else if (mkind == 2) keep = ((const float*)maskp)[midx] != 0.0f;
            else                 keep = ((const uint8_t*)maskp)[midx] != 0;
#pragma unroll
            for (int nt = 0; nt < 4; nt++) {
                int col = n0 + wn + nt * 8 + 2 * c;
                float v0 = keep ? (acc[mt][nt][rr * 2 + 0] + bias[col])     : 0.0f;
                float v1 = keep ? (acc[mt][nt][rr * 2 + 1] + bias[col + 1]) : 0.0f;
                *(float2*)&out[(size_t)row * EDIM + col] = make_float2(v0, v1);
            }
        }
}

// ============================================================================
// Kernel 2: flash attention. CTA = 128 q-rows x 1 head, 8 warps, 2 CTA/SM.
// 16 key-stages of 64 keys; 2-stage cp.async ring (2 barriers/stage).
// Q, K, V, P all rounded fp16 (single-pass MMA). Bias fp32 in swizzled smem.
// ============================================================================
#define ASTG 49152    // Kh 8192 + Vh 8192 + bias 32768 (128 rows x 64 f32, chunk-XOR)

__device__ __forceinline__ void attn_load_stage(
    uint32_t sbase, size_t kvbase, const float* bb, int m0, int n0, int tid)
{
    uint32_t kH = sbase, vH = sbase + 8192, bS = sbase + 16384;
#pragma unroll
    for (int it = 0; it < 2; it++) {
        int s = tid + it * 256;
        int row = s >> 3, ch = s & 7;
        uint32_t off = (uint32_t)(row * 128 + ((ch ^ (row & 7)) * 16));
        size_t gi = kvbase + (size_t)(m0 + row) * HD + ch * 8;
        cp16(kH + off, g_kh + gi);
        cp16(vH + off, g_vh + gi);
    }
    // bias: 128 rows x 16 chunks of 16B, chunk index XOR-swizzled by row
#pragma unroll
    for (int it = 0; it < 8; it++) {
        int s = tid + it * 256;
        int row = s >> 4, ch = s & 15;
        cp16(bS + (uint32_t)(row * 256 + ((ch ^ (row & 15)) << 4)),
             bb + (size_t)(n0 + row) * NNODE + m0 + ch * 4);
    }
}

__global__ __launch_bounds__(256, 2) void attn_kernel(const float* __restrict__ bias)
{
    extern __shared__ __align__(16) char dynsm[];
    const int tid = threadIdx.x, lane = tid & 31, warp = tid >> 5;
    const int bh = blockIdx.y, n0 = blockIdx.x * 128;
    const size_t base = (size_t)bh * NNODE * HD;
    const float* bb = bias + ((size_t)bh << 20);

    const uint32_t qH = smem_u32(dynsm);
    const uint32_t st0 = qH + 16384;

    // prologue: Q tile + stages 0,1
#pragma unroll
    for (int it = 0; it < 4; it++) {
        int s = tid + it * 256;
        int row = s >> 3, ch = s & 7;
        uint32_t off = (uint32_t)(row * 128 + ((ch ^ (row & 7)) * 16));
        cp16(qH + off, g_qh + base + (size_t)(n0 + row) * HD + ch * 8);
    }
    attn_load_stage(st0, base, bb, 0, n0, tid);
    cpcommit();
    attn_load_stage(st0 + ASTG, base, bb, 64, n0, tid);
    cpcommit();

    uint32_t qh[4][4];
    float o[8][4] = {};
    float mrow0 = -1e30f, mrow1 = -1e30f, lrow0 = 0.f, lrow1 = 0.f;
    const int g = lane >> 2, c = lane & 3;
    const int brow0 = warp * 16 + g, brow1 = brow0 + 8;

    for (int t = 0; t < 16; t++) {
        cpwait<1>();
        __syncthreads();
        if (t == 0) {
#pragma unroll
            for (int kc = 0; kc < 4; kc++) {
                int row = warp * 16 + (lane & 15);
                int ch = (kc * 2 + (lane >> 4)) ^ (row & 7);
                ldmx4(qh[kc][0], qh[kc][1], qh[kc][2], qh[kc][3], qH + row * 128 + ch * 16);
            }
        }

        const uint32_t cur = st0 + (t & 1) * ASTG;
        const uint32_t kH = cur, vH = cur + 8192;
        const char* bsm = dynsm + 16384 + (t & 1) * ASTG + 16384;

        // S = Qh Kh^T over 64 keys (single pass)
        float sfr[8][4] = {};
#pragma unroll
        for (int kc = 0; kc < 4; kc++) {
            uint32_t kbh[4][4];
#pragma unroll
            for (int pr = 0; pr < 4; pr++) {
                int row = pr * 16 + ((lane >> 4) << 3) + (lane & 7);
                int ch = (kc * 2 + ((lane >> 3) & 1)) ^ (row & 7);
                ldmx4(kbh[pr][0], kbh[pr][1], kbh[pr][2], kbh[pr][3], kH + row * 128 + ch * 16);
            }
#pragma unroll
            for (int nt = 0; nt < 8; nt++)
                mma16816(sfr[nt], qh[kc],
                         kbh[nt >> 1][(nt & 1) * 2], kbh[nt >> 1][(nt & 1) * 2 + 1]);
        }

        // bias (swizzled smem) + online softmax for rows brow0, brow1
        float mx0 = -1e30f, mx1 = -1e30f;
#pragma unroll
        for (int nt = 0; nt < 8; nt++) {
            int col = nt * 8 + 2 * c;
            int chunk = col >> 2, within = (col & 3) * 4;
            float2 b01 = *(const float2*)(bsm + brow0 * 256 + ((chunk ^ (brow0 & 15)) << 4) + within);
            float2 b23 = *(const float2*)(bsm + brow1 * 256 + ((chunk ^ (brow1 & 15)) << 4) + within);
            sfr[nt][0] += b01.x; sfr[nt][1] += b01.y;
            sfr[nt][2] += b23.x; sfr[nt][3] += b23.y;
            mx0 = fmaxf(mx0, fmaxf(sfr[nt][0], sfr[nt][1]));
            mx1 = fmaxf(mx1, fmaxf(sfr[nt][2], sfr[nt][3]));
        }
        mx0 = fmaxf(mx0, __shfl_xor_sync(0xffffffffu, mx0, 1));
        mx0 = fmaxf(mx0, __shfl_xor_sync(0xffffffffu, mx0, 2));
        mx1 = fmaxf(mx1, __shfl_xor_sync(0xffffffffu, mx1, 1));
        mx1 = fmaxf(mx1, __shfl_xor_sync(0xffffffffu, mx1, 2));
        float mn0 = fmaxf(mrow0, mx0), mn1 = fmaxf(mrow1, mx1);
        float al0 = __expf(mrow0 - mn0), al1 = __expf(mrow1 - mn1);
        mrow0 = mn0; mrow1 = mn1;
        float sum0 = 0.f, sum1 = 0.f;
#pragma unroll
        for (int nt = 0; nt < 8; nt++) {
            sfr[nt][0] = __expf(sfr[nt][0] - mn0);
            sfr[nt][1] = __expf(sfr[nt][1] - mn0);
            sfr[nt][2] = __expf(sfr[nt][2] - mn1);
            sfr[nt][3] = __expf(sfr[nt][3] - mn1);
            sum0 += sfr[nt][0] + sfr[nt][1];
            sum1 += sfr[nt][2] + sfr[nt][3];
        }
        sum0 += __shfl_xor_sync(0xffffffffu, sum0, 1);
        sum0 += __shfl_xor_sync(0xffffffffu, sum0, 2);
        sum1 += __shfl_xor_sync(0xffffffffu, sum1, 1);
        sum1 += __shfl_xor_sync(0xffffffffu, sum1, 2);
        lrow0 = lrow0 * al0 + sum0;
        lrow1 = lrow1 * al1 + sum1;
#pragma unroll
        for (int nt = 0; nt < 8; nt++) {
            o[nt][0] *= al0; o[nt][1] *= al0;
            o[nt][2] *= al1; o[nt][3] *= al1;
        }

        // O += Ph Vh (single pass)
#pragma unroll
        for (int kc = 0; kc < 4; kc++) {
            uint32_t pa[4];
            pa[0] = pack_half2(sfr[2 * kc][0],     sfr[2 * kc][1]);
            pa[1] = pack_half2(sfr[2 * kc][2],     sfr[2 * kc][3]);
            pa[2] = pack_half2(sfr[2 * kc + 1][0], sfr[2 * kc + 1][1]);
            pa[3] = pack_half2(sfr[2 * kc + 1][2], sfr[2 * kc + 1][3]);
#pragma unroll
            for (int pr = 0; pr < 4; pr++) {
                int row = kc * 16 + ((lane >> 3) & 1) * 8 + (lane & 7);
                int ch = (2 * pr + (lane >> 4)) ^ (row & 7);
                uint32_t vh0, vh1, vh2, vh3;
                ldmx4t(vh0, vh1, vh2, vh3, vH + row * 128 + ch * 16);
                mma16816(o[2 * pr],     pa, vh0, vh1);
                mma16816(o[2 * pr + 1], pa, vh2, vh3);
            }
        }

        // all warps done reading this slot before reloading it
        __syncthreads();
        if (t + 2 < 16)
            attn_load_stage(st0 + (t & 1) * ASTG, base, bb, (t + 2) * 64, n0, tid);
        cpcommit();
    }

    // epilogue: normalize, round to fp16, store [N, B, E]
    const float inv0 = 1.f / lrow0, inv1 = 1.f / lrow1;
    const int bg = bh / NH, hh = bh - bg * NH;
    const int r0g = n0 + warp * 16 + g;
#pragma unroll
    for (int nt = 0; nt < 8; nt++) {
        int d = nt * 8 + 2 * c;
        size_t i0 = ((size_t)r0g * NG + bg) * EDIM + hh * HD + d;
        size_t i1 = ((size_t)(r0g + 8) * NG + bg) * EDIM + hh * HD + d;
        *(uint32_t*)&g_ah[i0] = pack_half2(o[nt][0] * inv0, o[nt][1] * inv0);
        *(uint32_t*)&g_ah[i1] = pack_half2(o[nt][2] * inv1, o[nt][3] * inv1);
    }
}

// ---------------------------------------------------------------------------
extern "C" void kernel_launch(void* const* d_in, const int* in_sizes, int n_in,
                              void* d_out, int out_size) {
    const float* query     = (const float*)d_in[0];
    const float* attn_bias = (const float*)d_in[1];
    const void*  mask      = d_in[2];
    const float* W_in      = (const float*)d_in[3];
    const float* b_in      = (const float*)d_in[4];
    const float* W_out     = (const float*)d_in[5];
    const float* b_out     = (const float*)d_in[6];
    float* out = (float*)d_out;

    detect_mask_kernel<<<1, 256>>>((const uint8_t*)mask);
    prep_kernel<<<(NQ4 + NWI4 + NWO4 + 255) / 256, 256>>>(
        (const float4*)query, (const float4*)W_in, (const float4*)W_out);

    const int gsm = 3 * GSTG;  // 72 KB
    cudaFuncSetAttribute((const void*)qkv_gemm_kernel,
                         cudaFuncAttributeMaxDynamicSharedMemorySize, gsm);
    cudaFuncSetAttribute((const void*)out_gemm_kernel,
                         cudaFuncAttributeMaxDynamicSharedMemorySize, gsm);
    qkv_gemm_kernel<<<dim3(32, 18), 256, gsm>>>(b_in);

    const int asmb = 16384 + 2 * ASTG;  // 114688 -> 2 CTAs/SM
    cudaFuncSetAttribute((const void*)attn_kernel,
                         cudaFuncAttributeMaxDynamicSharedMemorySize, asmb);
    attn_kernel<<<dim3(8, BHD), 256, asmb>>>(attn_bias);

    out_gemm_kernel<<<dim3(32, 6), 256, gsm>>>(b_out, mask, out);
}

// round 7
// speedup vs baseline: 6.4263x; 1.1831x over previous
#include <cuda_runtime.h>
#include <cuda_fp16.h>
#include <cstdint>

#define NG    4
#define NH    12
#define BHD   48
#define NNODE 1024
#define EDIM  768
#define HD    64
#define QSCALE 0.125f
#define MROWS 4096

// ---------------- scratch (no cudaMalloc allowed) ----------------
__device__ __half g_qxh[MROWS * EDIM];       // query rounded fp16
__device__ __half g_wih[3 * EDIM * EDIM];    // W_in rounded
__device__ __half g_woh[EDIM * EDIM];        // W_out rounded
__device__ __half g_qh[BHD * NNODE * HD];    // q rounded (scaled)
__device__ __half g_kh[BHD * NNODE * HD];    // k rounded
__device__ __half g_vh[BHD * NNODE * HD];    // v rounded
__device__ __half g_ah[MROWS * EDIM];        // attn out rounded
__device__ int    g_mask_kind;

// ---------------- helpers ----------------
__device__ __forceinline__ uint32_t smem_u32(const void* p) {
    return (uint32_t)__cvta_generic_to_shared(p);
}
__device__ __forceinline__ void cp16(uint32_t dst, const void* src) {
    asm volatile("cp.async.cg.shared.global [%0],[%1],16;\n" :: "r"(dst), "l"(src) : "memory");
}
__device__ __forceinline__ void cpcommit() {
    asm volatile("cp.async.commit_group;\n" ::: "memory");
}
template<int N> __device__ __forceinline__ void cpwait() {
    asm volatile("cp.async.wait_group %0;\n" :: "n"(N) : "memory");
}
__device__ __forceinline__ void ldmx4(uint32_t& r0, uint32_t& r1, uint32_t& r2, uint32_t& r3, uint32_t a) {
    asm volatile("ldmatrix.sync.aligned.m8n8.x4.shared.b16 {%0,%1,%2,%3},[%4];\n"
                 : "=r"(r0), "=r"(r1), "=r"(r2), "=r"(r3) : "r"(a));
}
__device__ __forceinline__ void ldmx4t(uint32_t& r0, uint32_t& r1, uint32_t& r2, uint32_t& r3, uint32_t a) {
    asm volatile("ldmatrix.sync.aligned.m8n8.x4.trans.shared.b16 {%0,%1,%2,%3},[%4];\n"
                 : "=r"(r0), "=r"(r1), "=r"(r2), "=r"(r3) : "r"(a));
}
__device__ __forceinline__ void mma16816(float* c, const uint32_t* a, uint32_t b0, uint32_t b1) {
    asm volatile("mma.sync.aligned.m16n8k16.row.col.f32.f16.f16.f32 "
                 "{%0,%1,%2,%3},{%4,%5,%6,%7},{%8,%9},{%0,%1,%2,%3};\n"
                 : "+f"(c[0]), "+f"(c[1]), "+f"(c[2]), "+f"(c[3])
                 : "r"(a[0]), "r"(a[1]), "r"(a[2]), "r"(a[3]), "r"(b0), "r"(b1));
}
__device__ __forceinline__ uint32_t pack_half2(float x, float y) {
    __half2 h = __floats2half2_rn(x, y);
    return *reinterpret_cast<uint32_t*>(&h);
}

// ---------------- mask dtype probe ----------------
__global__ void detect_mask_kernel(const uint8_t* __restrict__ m) {
    __shared__ int or_b0, or_b123;
    if (threadIdx.x == 0) { or_b0 = 0; or_b123 = 0; }
    __syncthreads();
    int a0 = 0, a123 = 0;
    for (int w = threadIdx.x; w < 1024; w += blockDim.x) {
        a0   |= m[4 * w];
        a123 |= m[4 * w + 1] | m[4 * w + 2] | m[4 * w + 3];
    }
    if (a0)   atomicOr(&or_b0, 1);
    if (a123) atomicOr(&or_b123, 1);
    __syncthreads();
    if (threadIdx.x == 0) {
        if (or_b0 == 0)        g_mask_kind = 2;
        else if (or_b123 == 0) g_mask_kind = 1;
        else                   g_mask_kind = 0;
    }
}

// ---------------- fused prep: round query, W_in, W_out to fp16 ----------------
#define NQ4  (MROWS * EDIM / 4)          // 196608
#define NWI4 (3 * EDIM * EDIM / 4)       // 442368
#define NWO4 (EDIM * EDIM / 4)           // 147456
__global__ void prep_kernel(const float4* __restrict__ q,
                            const float4* __restrict__ wi,
                            const float4* __restrict__ wo) {
    int i = blockIdx.x * blockDim.x + threadIdx.x;
    if (i < NQ4) {
        float4 f = q[i];
        ((uint2*)g_qxh)[i] = make_uint2(pack_half2(f.x, f.y), pack_half2(f.z, f.w));
    } else if (i < NQ4 + NWI4) {
        int j = i - NQ4;
        float4 f = wi[j];
        ((uint2*)g_wih)[j] = make_uint2(pack_half2(f.x, f.y), pack_half2(f.z, f.w));
    } else if (i < NQ4 + NWI4 + NWO4) {
        int j = i - NQ4 - NWI4;
        float4 f = wo[j];
        ((uint2*)g_woh)[j] = make_uint2(pack_half2(f.x, f.y), pack_half2(f.z, f.w));
    }
}

// ============================================================================
// GEMM core: BM=128, BN=128, BK=32, 256 threads (8 warps 2x4), warp 64x32.
// A and B both rounded fp16, single-pass MMA. 3-stage cp.async ring.
// ============================================================================
#define GSTG 16384   // A 8192 + B 8192

__device__ __forceinline__ void gemm_load_stage(
    uint32_t sbase, const __half* A, const __half* B,
    int m0, int n0, int k0, int tid)
{
    uint32_t aH = sbase, bH = sbase + 8192;
#pragma unroll
    for (int it = 0; it < 2; it++) {
        int s = tid + it * 256;
        int row = s >> 2, sg = s & 3;
        uint32_t off = (uint32_t)(row * 64 + ((sg ^ (row & 3)) * 16));
        cp16(aH + off, A + (size_t)(m0 + row) * EDIM + k0 + sg * 8);
        cp16(bH + off, B + (size_t)(n0 + row) * EDIM + k0 + sg * 8);
    }
}

__device__ __forceinline__ void gemm_compute_stage(
    uint32_t sbase, int lane, int wm, int wn, float acc[4][4][4])
{
    uint32_t aH = sbase, bH = sbase + 8192;
#pragma unroll
    for (int kc = 0; kc < 2; kc++) {
        uint32_t ah[4][4], bh[2][4];
#pragma unroll
        for (int mt = 0; mt < 4; mt++) {
            int row = wm + mt * 16 + (lane & 15);
            int ch = (kc * 2 + (lane >> 4)) ^ (row & 3);
            ldmx4(ah[mt][0], ah[mt][1], ah[mt][2], ah[mt][3], aH + row * 64 + ch * 16);
        }
#pragma unroll
        for (int pr = 0; pr < 2; pr++) {
            int row = wn + pr * 16 + ((lane >> 4) << 3) + (lane & 7);
            int ch = (kc * 2 + ((lane >> 3) & 1)) ^ (row & 3);
            ldmx4(bh[pr][0], bh[pr][1], bh[pr][2], bh[pr][3], bH + row * 64 + ch * 16);
        }
#pragma unroll
        for (int mt = 0; mt < 4; mt++)
#pragma unroll
            for (int nt = 0; nt < 4; nt++)
                mma16816(acc[mt][nt], ah[mt],
                         bh[nt >> 1][(nt & 1) * 2], bh[nt >> 1][(nt & 1) * 2 + 1]);
    }
}

#define GEMM_PIPE(Aptr, Bptr)                                                 \
    extern __shared__ __align__(16) char dynsm[];                             \
    const int tid = threadIdx.x, lane = tid & 31, warp = tid >> 5;            \
    const int wm = (warp >> 2) * 64, wn = (warp & 3) * 32;                    \
    const int m0 = blockIdx.x * 128, n0 = blockIdx.y * 128;                   \
    const uint32_t sb = smem_u32(dynsm);                                      \
    gemm_load_stage(sb,        Aptr, Bptr, m0, n0, 0,  tid);                  \
    cpcommit();                                                               \
    gemm_load_stage(sb + GSTG, Aptr, Bptr, m0, n0, 32, tid);                  \
    cpcommit();                                                               \
    float acc[4][4][4] = {};                                                  \
    for (int kt = 0; kt < 24; kt++) {                                         \
        cpwait<1>();                                                          \
        __syncthreads();                                                      \
        gemm_compute_stage(sb + (kt % 3) * GSTG, lane, wm, wn, acc);          \
        if (kt + 2 < 24)                                                      \
            gemm_load_stage(sb + ((kt + 2) % 3) * GSTG, Aptr, Bptr,           \
                            m0, n0, (kt + 2) * 32, tid);                      \
        cpcommit();                                                           \
    }

// ---------------------------------------------------------------------------
// Kernel 1: qkv projection. Grid (32, 18).
// ---------------------------------------------------------------------------
__global__ __launch_bounds__(256, 2) void qkv_gemm_kernel(const float* __restrict__ bias)
{
    GEMM_PIPE(g_qxh, g_wih)

    const int g = lane >> 2, c = lane & 3;
    const int sec = n0 / EDIM;
    const int colbase = n0 - sec * EDIM;
    const float sc = (sec == 0) ? QSCALE : 1.0f;
    __half* dst = (sec == 0) ? g_qh : (sec == 1 ? g_kh : g_vh);
#pragma unroll
    for (int mt = 0; mt < 4; mt++)
#pragma unroll
        for (int nt = 0; nt < 4; nt++) {
            int dloc = wn + nt * 8 + 2 * c;
            int e = colbase + dloc;
            int hh = e >> 6, d = e & 63;
            float bv0 = bias[n0 + dloc], bv1 = bias[n0 + dloc + 1];
#pragma unroll
            for (int rr = 0; rr < 2; rr++) {
                int row = m0 + wm + mt * 16 + g + rr * 8;
                int node = row >> 2, bg = row & 3;
                float v0 = (acc[mt][nt][rr * 2 + 0] + bv0) * sc;
                float v1 = (acc[mt][nt][rr * 2 + 1] + bv1) * sc;
                size_t idx = (((size_t)(bg * NH + hh) * NNODE + node) * HD + d);
                *(uint32_t*)&dst[idx] = pack_half2(v0, v1);
            }
        }
}

// ---------------------------------------------------------------------------
// Kernel 3: out projection + mask. Grid (32, 6).
// ---------------------------------------------------------------------------
__global__ __launch_bounds__(256, 2) void out_gemm_kernel(
    const float* __restrict__ bias, const void* __restrict__ maskp,
    float* __restrict__ out)
{
    GEMM_PIPE(g_ah, g_woh)

    const int g = lane >> 2, c = lane & 3;
    const int mkind = g_mask_kind;
#pragma unroll
    for (int mt = 0; mt < 4; mt++)
#pragma unroll
        for (int rr = 0; rr < 2; rr++) {
            int row = m0 + wm + mt * 16 + g + rr * 8;
            int node = row >> 2, bg = row & 3;
            int midx = bg * NNODE + node;
            bool keep;
            if (mkind == 1)      keep = ((const int*)maskp)[midx] != 0;
            else if (mkind == 2) keep = ((const float*)maskp)[midx] != 0.0f;
            else                 keep = ((const uint8_t*)maskp)[midx] != 0;
#pragma unroll
            for (int nt = 0; nt < 4; nt++) {
                int col = n0 + wn + nt * 8 + 2 * c;
                float v0 = keep ? (acc[mt][nt][rr * 2 + 0] + bias[col])     : 0.0f;
                float v1 = keep ? (acc[mt][nt][rr * 2 + 1] + bias[col + 1]) : 0.0f;
                *(float2*)&out[(size_t)row * EDIM + col] = make_float2(v0, v1);
            }
        }
}

// ============================================================================
// Kernel 2: flash attention. CTA = 128 q-rows x 1 head, 8 warps, 2 CTA/SM.
// 16 key-stages of 64 keys; 2-stage cp.async ring.
// Q, K, V, P all rounded fp16. Bias fp32 in chunk-XOR swizzled smem.
// ============================================================================
#define ASTG 49152    // Kh 8192 + Vh 8192 + bias 32768

__device__ __forceinline__ void attn_load_stage(
    uint32_t sbase, size_t kvbase, const float* bb, int m0, int n0, int tid)
{
    uint32_t kH = sbase, vH = sbase + 8192, bS = sbase + 16384;
#pragma unroll
    for (int it = 0; it < 2; it++) {
        int s = tid + it * 256;
        int row = s >> 3, ch = s & 7;
        uint32_t off = (uint32_t)(row * 128 + ((ch ^ (row & 7)) * 16));
        size_t gi = kvbase + (size_t)(m0 + row) * HD + ch * 8;
        cp16(kH + off, g_kh + gi);
        cp16(vH + off, g_vh + gi);
    }
#pragma unroll
    for (int it = 0; it < 8; it++) {
        int s = tid + it * 256;
        int row = s >> 4, ch = s & 15;
        cp16(bS + (uint32_t)(row * 256 + ((ch ^ (row & 15)) << 4)),
             bb + (size_t)(n0 + row) * NNODE + m0 + ch * 4);
    }
}

__global__ __launch_bounds__(256, 2) void attn_kernel(const float* __restrict__ bias)
{
    extern __shared__ __align__(16) char dynsm[];
    const int tid = threadIdx.x, lane = tid & 31, warp = tid >> 5;
    const int bh = blockIdx.y, n0 = blockIdx.x * 128;
    const size_t base = (size_t)bh * NNODE * HD;
    const float* bb = bias + ((size_t)bh << 20);

    const uint32_t qH = smem_u32(dynsm);
    const uint32_t st0 = qH + 16384;

    // prologue: Q tile + stages 0,1
#pragma unroll
    for (int it = 0; it < 4; it++) {
        int s = tid + it * 256;
        int row = s >> 3, ch = s & 7;
        uint32_t off = (uint32_t)(row * 128 + ((ch ^ (row & 7)) * 16));
        cp16(qH + off, g_qh + base + (size_t)(n0 + row) * HD + ch * 8);
    }
    attn_load_stage(st0, base, bb, 0, n0, tid);
    cpcommit();
    attn_load_stage(st0 + ASTG, base, bb, 64, n0, tid);
    cpcommit();

    uint32_t qh[4][4];
    float o[8][4] = {};
    float mrow0 = -1e30f, mrow1 = -1e30f, lrow0 = 0.f, lrow1 = 0.f;
    const int g = lane >> 2, c = lane & 3;
    const int brow0 = warp * 16 + g, brow1 = brow0 + 8;

    for (int t = 0; t < 16; t++) {
        cpwait<1>();
        __syncthreads();
        if (t == 0) {
#pragma unroll
            for (int kc = 0; kc < 4; kc++) {
                int row = warp * 16 + (lane & 15);
                int ch = (kc * 2 + (lane >> 4)) ^ (row & 7);
                ldmx4(qh[kc][0], qh[kc][1], qh[kc][2], qh[kc][3], qH + row * 128 + ch * 16);
            }
        }

        const uint32_t cur = st0 + (t & 1) * ASTG;
        const uint32_t kH = cur, vH = cur + 8192;
        const char* bsm = dynsm + 16384 + (t & 1) * ASTG + 16384;

        // S = Qh Kh^T over 64 keys (single pass)
        float sfr[8][4] = {};
#pragma unroll
        for (int kc = 0; kc < 4; kc++) {
            uint32_t kbh[4][4];
#pragma unroll
            for (int pr = 0; pr < 4; pr++) {
                int row = pr * 16 + ((lane >> 4) << 3) + (lane & 7);
                int ch = (kc * 2 + ((lane >> 3) & 1)) ^ (row & 7);
                ldmx4(kbh[pr][0], kbh[pr][1], kbh[pr][2], kbh[pr][3], kH + row * 128 + ch * 16);
            }
#pragma unroll
            for (int nt = 0; nt < 8; nt++)
                mma16816(sfr[nt], qh[kc],
                         kbh[nt >> 1][(nt & 1) * 2], kbh[nt >> 1][(nt & 1) * 2 + 1]);
        }

        // bias (swizzled smem) + online softmax for rows brow0, brow1
        float mx0 = -1e30f, mx1 = -1e30f;
#pragma unroll
        for (int nt = 0; nt < 8; nt++) {
            int col = nt * 8 + 2 * c;
            int chunk = col >> 2, within = (col & 3) * 4;
            float2 b01 = *(const float2*)(bsm + brow0 * 256 + ((chunk ^ (brow0 & 15)) << 4) + within);
            float2 b23 = *(const float2*)(bsm + brow1 * 256 + ((chunk ^ (brow1 & 15)) << 4) + within);
            sfr[nt][0] += b01.x; sfr[nt][1] += b01.y;
            sfr[nt][2] += b23.x; sfr[nt][3] += b23.y;
            mx0 = fmaxf(mx0, fmaxf(sfr[nt][0], sfr[nt][1]));
            mx1 = fmaxf(mx1, fmaxf(sfr[nt][2], sfr[nt][3]));
        }
        mx0 = fmaxf(mx0, __shfl_xor_sync(0xffffffffu, mx0, 1));
        mx0 = fmaxf(mx0, __shfl_xor_sync(0xffffffffu, mx0, 2));
        mx1 = fmaxf(mx1, __shfl_xor_sync(0xffffffffu, mx1, 1));
        mx1 = fmaxf(mx1, __shfl_xor_sync(0xffffffffu, mx1, 2));
        float mn0 = fmaxf(mrow0, mx0), mn1 = fmaxf(mrow1, mx1);
        // exact: when max unchanged, alpha = 1 and rescale is a no-op
        float al0 = (mn0 == mrow0) ? 1.0f : __expf(mrow0 - mn0);
        float al1 = (mn1 == mrow1) ? 1.0f : __expf(mrow1 - mn1);
        mrow0 = mn0; mrow1 = mn1;
        float sum0 = 0.f, sum1 = 0.f;
#pragma unroll
        for (int nt = 0; nt < 8; nt++) {
            sfr[nt][0] = __expf(sfr[nt][0] - mn0);
            sfr[nt][1] = __expf(sfr[nt][1] - mn0);
            sfr[nt][2] = __expf(sfr[nt][2] - mn1);
            sfr[nt][3] = __expf(sfr[nt][3] - mn1);
            sum0 += sfr[nt][0] + sfr[nt][1];
            sum1 += sfr[nt][2] + sfr[nt][3];
        }
        sum0 += __shfl_xor_sync(0xffffffffu, sum0, 1);
        sum0 += __shfl_xor_sync(0xffffffffu, sum0, 2);
        sum1 += __shfl_xor_sync(0xffffffffu, sum1, 1);
        sum1 += __shfl_xor_sync(0xffffffffu, sum1, 2);
        lrow0 = lrow0 * al0 + sum0;
        lrow1 = lrow1 * al1 + sum1;
        if ((al0 != 1.0f) || (al1 != 1.0f)) {
#pragma unroll
            for (int nt = 0; nt < 8; nt++) {
                o[nt][0] *= al0; o[nt][1] *= al0;
                o[nt][2] *= al1; o[nt][3] *= al1;
            }
        }

        // O += Ph Vh (single pass)
#pragma unroll
        for (int kc = 0; kc < 4; kc++) {
            uint32_t pa[4];
            pa[0] = pack_half2(sfr[2 * kc][0],     sfr[2 * kc][1]);
            pa[1] = pack_half2(sfr[2 * kc][2],     sfr[2 * kc][3]);
            pa[2] = pack_half2(sfr[2 * kc + 1][0], sfr[2 * kc + 1][1]);
            pa[3] = pack_half2(sfr[2 * kc + 1][2], sfr[2 * kc + 1][3]);
#pragma unroll
            for (int pr = 0; pr < 4; pr++) {
                int row = kc * 16 + ((lane >> 3) & 1) * 8 + (lane & 7);
                int ch = (2 * pr + (lane >> 4)) ^ (row & 7);
                uint32_t vh0, vh1, vh2, vh3;
                ldmx4t(vh0, vh1, vh2, vh3, vH + row * 128 + ch * 16);
                mma16816(o[2 * pr],     pa, vh0, vh1);
                mma16816(o[2 * pr + 1], pa, vh2, vh3);
            }
        }

        __syncthreads();
        if (t + 2 < 16)
            attn_load_stage(st0 + (t & 1) * ASTG, base, bb, (t + 2) * 64, n0, tid);
        cpcommit();
    }

    // epilogue: normalize, round to fp16, store [N, B, E]
    const float inv0 = 1.f / lrow0, inv1 = 1.f / lrow1;
    const int bg = bh / NH, hh = bh - bg * NH;
    const int r0g = n0 + warp * 16 + g;
#pragma unroll
    for (int nt = 0; nt < 8; nt++) {
        int d = nt * 8 + 2 * c;
        size_t i0 = ((size_t)r0g * NG + bg) * EDIM + hh * HD + d;
        size_t i1 = ((size_t)(r0g + 8) * NG + bg) * EDIM + hh * HD + d;
        *(uint32_t*)&g_ah[i0] = pack_half2(o[nt][0] * inv0, o[nt][1] * inv0);
        *(uint32_t*)&g_ah[i1] = pack_half2(o[nt][2] * inv1, o[nt][3] * inv1);
    }
}

// ---------------------------------------------------------------------------
extern "C" void kernel_launch(void* const* d_in, const int* in_sizes, int n_in,
                              void* d_out, int out_size) {
    const float* query     = (const float*)d_in[0];
    const float* attn_bias = (const float*)d_in[1];
    const void*  mask      = d_in[2];
    const float* W_in      = (const float*)d_in[3];
    const float* b_in      = (const float*)d_in[4];
    const float* W_out     = (const float*)d_in[5];
    const float* b_out     = (const float*)d_in[6];
    float* out = (float*)d_out;

    detect_mask_kernel<<<1, 256>>>((const uint8_t*)mask);
    prep_kernel<<<(NQ4 + NWI4 + NWO4 + 255) / 256, 256>>>(
        (const float4*)query, (const float4*)W_in, (const float4*)W_out);

    const int gsm = 3 * GSTG;  // 48 KB
    cudaFuncSetAttribute((const void*)qkv_gemm_kernel,
                         cudaFuncAttributeMaxDynamicSharedMemorySize, gsm);
    cudaFuncSetAttribute((const void*)out_gemm_kernel,
                         cudaFuncAttributeMaxDynamicSharedMemorySize, gsm);
    qkv_gemm_kernel<<<dim3(32, 18), 256, gsm>>>(b_in);

    const int asmb = 16384 + 2 * ASTG;  // 114688 -> 2 CTAs/SM
    cudaFuncSetAttribute((const void*)attn_kernel,
                         cudaFuncAttributeMaxDynamicSharedMemorySize, asmb);
    attn_kernel<<<dim3(8, BHD), 256, asmb>>>(attn_bias);

    out_gemm_kernel<<<dim3(32, 6), 256, gsm>>>(b_out, mask, out);
}